// round 8
// baseline (speedup 1.0000x reference)
#include <cuda_runtime.h>
#include <cuda_bf16.h>

#define NA   8
#define BSZ  4
#define THW  1024
#define DD   512
#define DA   64
#define NROWS (BSZ*THW)   // 4096
#define NQKV (3*NA*DA)    // 1536
#define STG  49152        // one GEMM pipeline stage: Ah16K|Al16K|Bh8K|Bl8K

// ---------------- device scratch (allocation forbidden) ----------------
__device__ __nv_bfloat16 g_xh[NROWS*DD], g_xl[NROWS*DD];          // normalized x hi/lo
__device__ __nv_bfloat16 g_qh[NA*NROWS*DA], g_ql[NA*NROWS*DA];    // q (pre-scaled 1/8)
__device__ __nv_bfloat16 g_kh[NA*NROWS*DA], g_kl[NA*NROWS*DA];
__device__ __nv_bfloat16 g_vh[NA*NROWS*DA], g_vl[NA*NROWS*DA];
__device__ __nv_bfloat16 g_aoh[NROWS*DD], g_aol[NROWS*DD];        // concat attn out hi/lo
__device__ __nv_bfloat16 g_wth[NQKV*DD], g_wtl[NQKV*DD];          // qkv weights, [n][d]
__device__ __nv_bfloat16 g_wph[DD*DD],  g_wpl[DD*DD];             // proj weights, [o][i]

// ---------------- helpers ----------------
__device__ __forceinline__ void mma4(float c[4], const unsigned a[4], unsigned b0, unsigned b1) {
    asm volatile(
        "mma.sync.aligned.m16n8k16.row.col.f32.bf16.bf16.f32 "
        "{%0,%1,%2,%3}, {%4,%5,%6,%7}, {%8,%9}, {%0,%1,%2,%3};\n"
        : "+f"(c[0]), "+f"(c[1]), "+f"(c[2]), "+f"(c[3])
        : "r"(a[0]), "r"(a[1]), "r"(a[2]), "r"(a[3]), "r"(b0), "r"(b1));
}

__device__ __forceinline__ void ldsm4(unsigned& r0, unsigned& r1, unsigned& r2, unsigned& r3,
                                      const void* p) {
    unsigned addr = (unsigned)__cvta_generic_to_shared(p);
    asm volatile("ldmatrix.sync.aligned.m8n8.x4.shared.b16 {%0,%1,%2,%3}, [%4];"
                 : "=r"(r0), "=r"(r1), "=r"(r2), "=r"(r3) : "r"(addr));
}

__device__ __forceinline__ void ldsm4t(unsigned& r0, unsigned& r1, unsigned& r2, unsigned& r3,
                                       const void* p) {
    unsigned addr = (unsigned)__cvta_generic_to_shared(p);
    asm volatile("ldmatrix.sync.aligned.m8n8.x4.trans.shared.b16 {%0,%1,%2,%3}, [%4];"
                 : "=r"(r0), "=r"(r1), "=r"(r2), "=r"(r3) : "r"(addr));
}

__device__ __forceinline__ void cpa16(void* dst, const void* src) {
    unsigned d = (unsigned)__cvta_generic_to_shared(dst);
    asm volatile("cp.async.cg.shared.global [%0], [%1], 16;" :: "r"(d), "l"(src));
}
__device__ __forceinline__ void cp_commit() {
    asm volatile("cp.async.commit_group;" ::: "memory");
}
template<int N> __device__ __forceinline__ void cp_wait() {
    asm volatile("cp.async.wait_group %0;" :: "n"(N) : "memory");
}

__device__ __forceinline__ void split1(float x, __nv_bfloat16& h, __nv_bfloat16& l) {
    h = __float2bfloat16_rn(x);
    l = __float2bfloat16_rn(x - __bfloat162float(h));
}

__device__ __forceinline__ void split_pair(float a, float b, unsigned& hi, unsigned& lo) {
    __nv_bfloat16 ah = __float2bfloat16_rn(a), bh = __float2bfloat16_rn(b);
    float ar = a - __bfloat162float(ah), br = b - __bfloat162float(bh);
    __nv_bfloat162 h2; h2.x = ah; h2.y = bh;
    __nv_bfloat162 l2; l2.x = __float2bfloat16_rn(ar); l2.y = __float2bfloat16_rn(br);
    hi = *reinterpret_cast<unsigned*>(&h2);
    lo = *reinterpret_cast<unsigned*>(&l2);
}

// ---------------------------------------------------------------- LayerNorm
__global__ void ln_kernel(const float* __restrict__ x,
                          const float* __restrict__ gamma,
                          const float* __restrict__ beta) {
    int row = blockIdx.x;
    int t   = threadIdx.x;              // 128 threads
    const float* xr = x + (size_t)row * DD;
    float v[4];
    float s = 0.f;
#pragma unroll
    for (int i = 0; i < 4; i++) { v[i] = xr[i * 128 + t]; s += v[i]; }

    __shared__ float rbuf[4];
    __shared__ float stat;
#pragma unroll
    for (int o = 16; o > 0; o >>= 1) s += __shfl_xor_sync(0xffffffffu, s, o);
    if ((t & 31) == 0) rbuf[t >> 5] = s;
    __syncthreads();
    if (t == 0) stat = rbuf[0] + rbuf[1] + rbuf[2] + rbuf[3];
    __syncthreads();
    float mean = stat * (1.f / DD);

    float ss = 0.f;
#pragma unroll
    for (int i = 0; i < 4; i++) { float d = v[i] - mean; ss += d * d; }
    __syncthreads();
#pragma unroll
    for (int o = 16; o > 0; o >>= 1) ss += __shfl_xor_sync(0xffffffffu, ss, o);
    if ((t & 31) == 0) rbuf[t >> 5] = ss;
    __syncthreads();
    if (t == 0) stat = rbuf[0] + rbuf[1] + rbuf[2] + rbuf[3];
    __syncthreads();
    float rstd = rsqrtf(stat * (1.f / DD) + 1e-5f);

#pragma unroll
    for (int i = 0; i < 4; i++) {
        int c = i * 128 + t;
        float y = (v[i] - mean) * rstd * gamma[c] + beta[c];
        __nv_bfloat16 h, l; split1(y, h, l);
        g_xh[(size_t)row * DD + c] = h;
        g_xl[(size_t)row * DD + c] = l;
    }
}

// ------------------------------------------------- weight prep (smem transpose)
// Wt[n][d], n = which*512 + h*64 + e, bf16 hi/lo.  grid 24 blocks x 256 thr.
__global__ void prep_w(const float* __restrict__ wq,
                       const float* __restrict__ wk,
                       const float* __restrict__ wv) {
    __shared__ float tile[64][65];
    int which = blockIdx.x >> 3, h = blockIdx.x & 7;
    const float* w = ((which == 0) ? wq : (which == 1) ? wk : wv) + (size_t)h * DD * DA;
    int n0 = which * 512 + h * 64;

    for (int d0 = 0; d0 < DD; d0 += 64) {
#pragma unroll
        for (int it = 0; it < 16; it++) {
            int idx = it * 256 + threadIdx.x;    // 4096
            int r = idx >> 6, e = idx & 63;
            tile[r][e] = w[(size_t)(d0 + r) * DA + e];
        }
        __syncthreads();
#pragma unroll
        for (int it = 0; it < 8; it++) {
            int idx = it * 256 + threadIdx.x;    // 2048
            int e = idx >> 5, j = idx & 31;
            unsigned hi, lo;
            split_pair(tile[2 * j][e], tile[2 * j + 1][e], hi, lo);
            *(unsigned*)(g_wth + (size_t)(n0 + e) * DD + d0 + 2 * j) = hi;
            *(unsigned*)(g_wtl + (size_t)(n0 + e) * DD + d0 + 2 * j) = lo;
        }
        __syncthreads();
    }
}

__global__ void prep_wp(const float* __restrict__ wp) {
    size_t p = (size_t)blockIdx.x * 256 + threadIdx.x;   // grid 512
    float2 v = ((const float2*)wp)[p];
    unsigned hi, lo; split_pair(v.x, v.y, hi, lo);
    ((unsigned*)g_wph)[p] = hi;
    ((unsigned*)g_wpl)[p] = lo;
}

// ---------------------------------------------------------------- big GEMM
// C[128m x 64n] per block, 8 warps (4m x 2n), warp 32x32, k-tile 64.
// Double-buffered cp.async pipeline, 2 stages x 48KB dynamic smem.
struct GemmAcc { float c[2][4][4]; };

__device__ __forceinline__ void gemm_stage_load(
    const __nv_bfloat16* Asrc_h, const __nv_bfloat16* Asrc_l,
    const __nv_bfloat16* Bsrc_h, const __nv_bfloat16* Bsrc_l,
    char* S, int tid, int k0)
{
#pragma unroll
    for (int it = 0; it < 4; it++) {
        int flat = it * 256 + tid;
        int r = flat >> 3, cc = flat & 7;
        size_t so = (size_t)r * DD + k0 + cc * 8;
        int off = r * 128 + ((cc ^ (r & 7)) << 4);
        cpa16(S + off,         Asrc_h + so);
        cpa16(S + 16384 + off, Asrc_l + so);
    }
#pragma unroll
    for (int it = 0; it < 2; it++) {
        int flat = it * 256 + tid;
        int r = flat >> 3, cc = flat & 7;
        size_t so = (size_t)r * DD + k0 + cc * 8;
        int off = r * 128 + ((cc ^ (r & 7)) << 4);
        cpa16(S + 32768 + off, Bsrc_h + so);
        cpa16(S + 40960 + off, Bsrc_l + so);
    }
    cp_commit();
}

__device__ __forceinline__ void gemm_stage_compute(
    char* S, int mw, int nw, int grp, int li, GemmAcc& acc)
{
    char* Ah = S;
    char* Al = S + 16384;
    char* Bh = S + 32768;
    char* Bl = S + 40960;
#pragma unroll
    for (int s4 = 0; s4 < 4; s4++) {
        unsigned afh[2][4], afl[2][4];
#pragma unroll
        for (int mi = 0; mi < 2; mi++) {
            int ar = mw + mi * 16 + ((grp & 1) << 3) + li;
            int sw = (((s4 * 2 + (grp >> 1)) ^ (ar & 7)) << 4);
            ldsm4(afh[mi][0], afh[mi][1], afh[mi][2], afh[mi][3], Ah + ar * 128 + sw);
            ldsm4(afl[mi][0], afl[mi][1], afl[mi][2], afl[mi][3], Al + ar * 128 + sw);
        }
        unsigned bfh[2][4], bfl[2][4];
#pragma unroll
        for (int jp = 0; jp < 2; jp++) {
            int br = nw + jp * 16 + ((grp >> 1) << 3) + li;
            int sw = (((s4 * 2 + (grp & 1)) ^ (br & 7)) << 4);
            ldsm4(bfh[jp][0], bfh[jp][1], bfh[jp][2], bfh[jp][3], Bh + br * 128 + sw);
            ldsm4(bfl[jp][0], bfl[jp][1], bfl[jp][2], bfl[jp][3], Bl + br * 128 + sw);
        }
#pragma unroll
        for (int mi = 0; mi < 2; mi++)
#pragma unroll
            for (int jp = 0; jp < 2; jp++) {
                float* c0 = acc.c[mi][jp * 2];
                float* c1 = acc.c[mi][jp * 2 + 1];
                mma4(c0, afh[mi], bfh[jp][0], bfh[jp][1]);
                mma4(c0, afl[mi], bfh[jp][0], bfh[jp][1]);
                mma4(c0, afh[mi], bfl[jp][0], bfl[jp][1]);
                mma4(c1, afh[mi], bfh[jp][2], bfh[jp][3]);
                mma4(c1, afl[mi], bfh[jp][2], bfh[jp][3]);
                mma4(c1, afh[mi], bfl[jp][2], bfl[jp][3]);
            }
    }
}

__device__ __forceinline__ void gemm_mainloop(
    const __nv_bfloat16* Asrc_h, const __nv_bfloat16* Asrc_l,
    const __nv_bfloat16* Bsrc_h, const __nv_bfloat16* Bsrc_l,
    char* sm, int tid, int mw, int nw, int grp, int li, GemmAcc& acc)
{
    gemm_stage_load(Asrc_h, Asrc_l, Bsrc_h, Bsrc_l, sm, tid, 0);
    const int NK = DD / 64;   // 8
#pragma unroll 1
    for (int kt = 0; kt < NK; kt++) {
        if (kt < NK - 1) {
            gemm_stage_load(Asrc_h, Asrc_l, Bsrc_h, Bsrc_l,
                            sm + ((kt + 1) & 1) * STG, tid, (kt + 1) * 64);
            cp_wait<1>();
        } else {
            cp_wait<0>();
        }
        __syncthreads();
        gemm_stage_compute(sm + (kt & 1) * STG, mw, nw, grp, li, acc);
        __syncthreads();
    }
}

// qkv GEMM: grid (4096/128, 1536/64), 256 thr, dynamic smem 96KB
__global__ __launch_bounds__(256, 2) void qkv_g() {
    extern __shared__ __align__(16) char smd[];
    int m0 = blockIdx.x * 128, n0 = blockIdx.y * 64;
    int which = n0 >> 9, h = (n0 >> 6) & 7;

    int tid = threadIdx.x, lane = tid & 31, wid = tid >> 5;
    int g = lane >> 2, tg = lane & 3, grp = lane >> 3, li = lane & 7;
    int mw = (wid >> 1) * 32, nw = (wid & 1) * 32;

    GemmAcc acc = {};
    gemm_mainloop(g_xh + (size_t)m0 * DD, g_xl + (size_t)m0 * DD,
                  g_wth + (size_t)n0 * DD, g_wtl + (size_t)n0 * DD,
                  smd, tid, mw, nw, grp, li, acc);

    float scale = (which == 0) ? 0.125f : 1.0f;
    __nv_bfloat16* oh = (which == 0) ? g_qh : ((which == 1) ? g_kh : g_vh);
    __nv_bfloat16* ol = (which == 0) ? g_ql : ((which == 1) ? g_kl : g_vl);
#pragma unroll
    for (int mi = 0; mi < 2; mi++)
#pragma unroll
        for (int nj = 0; nj < 4; nj++) {
            int m = m0 + mw + mi * 16 + g;
            int e = nw + nj * 8 + 2 * tg;
            unsigned hi, lo;
            split_pair(acc.c[mi][nj][0] * scale, acc.c[mi][nj][1] * scale, hi, lo);
            *(unsigned*)(oh + ((size_t)(h * NROWS + m)) * DA + e) = hi;
            *(unsigned*)(ol + ((size_t)(h * NROWS + m)) * DA + e) = lo;
            split_pair(acc.c[mi][nj][2] * scale, acc.c[mi][nj][3] * scale, hi, lo);
            *(unsigned*)(oh + ((size_t)(h * NROWS + m + 8)) * DA + e) = hi;
            *(unsigned*)(ol + ((size_t)(h * NROWS + m + 8)) * DA + e) = lo;
        }
}

// proj GEMM + residual: grid (4096/128, 512/64), 256 thr, dynamic smem 96KB
__global__ __launch_bounds__(256, 2) void proj_g(const float* __restrict__ x,
                                                 float* __restrict__ out) {
    extern __shared__ __align__(16) char smd[];
    int m0 = blockIdx.x * 128, n0 = blockIdx.y * 64;

    int tid = threadIdx.x, lane = tid & 31, wid = tid >> 5;
    int g = lane >> 2, tg = lane & 3, grp = lane >> 3, li = lane & 7;
    int mw = (wid >> 1) * 32, nw = (wid & 1) * 32;

    GemmAcc acc = {};
    gemm_mainloop(g_aoh + (size_t)m0 * DD, g_aol + (size_t)m0 * DD,
                  g_wph + (size_t)n0 * DD, g_wpl + (size_t)n0 * DD,
                  smd, tid, mw, nw, grp, li, acc);

#pragma unroll
    for (int mi = 0; mi < 2; mi++)
#pragma unroll
        for (int nj = 0; nj < 4; nj++) {
            int m = m0 + mw + mi * 16 + g;
            int n = n0 + nw + nj * 8 + 2 * tg;
#pragma unroll
            for (int rr = 0; rr < 2; rr++) {
                size_t off = (size_t)(m + rr * 8) * DD + n;
                float2 xr = *(const float2*)&x[off];
                float2 r;
                r.x = acc.c[mi][nj][rr * 2 + 0] + xr.x;
                r.y = acc.c[mi][nj][rr * 2 + 1] + xr.y;
                *(float2*)&out[off] = r;
            }
        }
}

// ---------------------------------------------------------------- fused attention
// grid (THW/128, NA*BSZ), 256 threads (8 warps, m16 each). k-tile = 32 tokens,
// double-buffered stages of 16KB (Kh 4K | Kl 4K | Vh 4K | Vl 4K).
__global__ __launch_bounds__(256) void attn_kernel(const float* __restrict__ Bb,
                                                   const int* __restrict__ M) {
    __shared__ __align__(16) char sm[2][16384];

    int hb = blockIdx.y;
    int h = hb >> 2, b = hb & 3;
    int qr0 = blockIdx.x * 128;

    int tid = threadIdx.x, lane = tid & 31, wid = tid >> 5;
    int g = lane >> 2, tg = lane & 3, grp = lane >> 3, li = lane & 7;
    int mw = wid * 16;

    size_t kv = (size_t)(h * NROWS + b * THW) * DA;

    // ---- Q tile into sm[0](hi)/sm[1](lo), extract frags ----
#pragma unroll
    for (int it = 0; it < 4; it++) {
        int flat = it * 256 + tid;
        int r = flat >> 3, cc = flat & 7;
        size_t so = kv + (size_t)(qr0 + r) * DA + cc * 8;
        int off = r * 128 + ((cc ^ (r & 7)) << 4);
        cpa16(sm[0] + off, g_qh + so);
        cpa16(sm[1] + off, g_ql + so);
    }
    cp_commit();
    cp_wait<0>();
    __syncthreads();

    unsigned qfh[4][4], qfl[4][4];
    {
        int qrow = mw + ((grp & 1) << 3) + li;
        int q7 = qrow & 7;
#pragma unroll
        for (int s4 = 0; s4 < 4; s4++) {
            int sw = (((s4 * 2 + (grp >> 1)) ^ q7) << 4);
            ldsm4(qfh[s4][0], qfh[s4][1], qfh[s4][2], qfh[s4][3], sm[0] + qrow * 128 + sw);
            ldsm4(qfl[s4][0], qfl[s4][1], qfl[s4][2], qfl[s4][3], sm[1] + qrow * 128 + sw);
        }
    }
    __syncthreads();

    // prefetch stage 0
    {
        int r = tid >> 3, cc = tid & 7;
        size_t so = kv + (size_t)r * DA + cc * 8;
        int off = r * 128 + ((cc ^ (r & 7)) << 4);
        cpa16(sm[0] + off,         g_kh + so);
        cpa16(sm[0] + 4096 + off,  g_kl + so);
        cpa16(sm[0] + 8192 + off,  g_vh + so);
        cpa16(sm[0] + 12288 + off, g_vl + so);
        cp_commit();
    }

    float m0 = -1e30f, m1 = -1e30f, l0 = 0.f, l1 = 0.f;
    float O[8][4] = {};

    const float* Brow = Bb + ((size_t)hb * THW + (qr0 + mw + g)) * THW + 2 * tg;
    const int*   Mrow = M  + (size_t)(qr0 + mw + g) * THW + 2 * tg;

    int pr = tid >> 3, pc = tid & 7;
    int poff = pr * 128 + ((pc ^ (pr & 7)) << 4);

    for (int kt = 0; kt < 32; kt++) {
        if (kt < 31) {
            char* S = sm[(kt + 1) & 1];
            size_t so = kv + (size_t)((kt + 1) * 32 + pr) * DA + pc * 8;
            cpa16(S + poff,         g_kh + so);
            cpa16(S + 4096 + poff,  g_kl + so);
            cpa16(S + 8192 + poff,  g_vh + so);
            cpa16(S + 12288 + poff, g_vl + so);
            cp_commit();
            cp_wait<1>();
        } else {
            cp_wait<0>();
        }
        __syncthreads();
        char* S = sm[kt & 1];

        // ---- S = Q K^T (3-MMA split), 32 kcols -> sc[4][4] ----
        float sc[4][4] = {};
#pragma unroll
        for (int s4 = 0; s4 < 4; s4++) {
#pragma unroll
            for (int jp = 0; jp < 2; jp++) {
                int rr = jp * 16 + ((grp >> 1) << 3) + li;
                int sw = (((s4 * 2 + (grp & 1)) ^ (rr & 7)) << 4);
                unsigned h0, h1, h2, h3, e0, e1, e2, e3;
                ldsm4(h0, h1, h2, h3, S + rr * 128 + sw);
                ldsm4(e0, e1, e2, e3, S + 4096 + rr * 128 + sw);
                mma4(sc[2*jp],   qfh[s4], h0, h1);
                mma4(sc[2*jp],   qfl[s4], h0, h1);
                mma4(sc[2*jp],   qfh[s4], e0, e1);
                mma4(sc[2*jp+1], qfh[s4], h2, h3);
                mma4(sc[2*jp+1], qfl[s4], h2, h3);
                mma4(sc[2*jp+1], qfh[s4], e2, e3);
            }
        }

        // ---- bias + mask ----
        const float* Bp = Brow + kt * 32;
        const int*   Mp = Mrow + kt * 32;
#pragma unroll
        for (int j = 0; j < 4; j++) {
            float2 b0 = *(const float2*)(Bp + j * 8);
            int2   i0 = *(const int2*)  (Mp + j * 8);
            sc[j][0] = i0.x ? -10000.f : sc[j][0] + b0.x;
            sc[j][1] = i0.y ? -10000.f : sc[j][1] + b0.y;
            float2 b1 = *(const float2*)(Bp + 8 * THW + j * 8);
            int2   i1 = *(const int2*)  (Mp + 8 * THW + j * 8);
            sc[j][2] = i1.x ? -10000.f : sc[j][2] + b1.x;
            sc[j][3] = i1.y ? -10000.f : sc[j][3] + b1.y;
        }

        // ---- online softmax ----
        float rm0 = -1e30f, rm1 = -1e30f;
#pragma unroll
        for (int j = 0; j < 4; j++) {
            rm0 = fmaxf(rm0, fmaxf(sc[j][0], sc[j][1]));
            rm1 = fmaxf(rm1, fmaxf(sc[j][2], sc[j][3]));
        }
        rm0 = fmaxf(rm0, __shfl_xor_sync(0xffffffffu, rm0, 1));
        rm0 = fmaxf(rm0, __shfl_xor_sync(0xffffffffu, rm0, 2));
        rm1 = fmaxf(rm1, __shfl_xor_sync(0xffffffffu, rm1, 1));
        rm1 = fmaxf(rm1, __shfl_xor_sync(0xffffffffu, rm1, 2));
        float nm0 = fmaxf(m0, rm0), nm1 = fmaxf(m1, rm1);
        float a0 = __expf(m0 - nm0), a1 = __expf(m1 - nm1);
        float ls0 = 0.f, ls1 = 0.f;
#pragma unroll
        for (int j = 0; j < 4; j++) {
            sc[j][0] = __expf(sc[j][0] - nm0); ls0 += sc[j][0];
            sc[j][1] = __expf(sc[j][1] - nm0); ls0 += sc[j][1];
            sc[j][2] = __expf(sc[j][2] - nm1); ls1 += sc[j][2];
            sc[j][3] = __expf(sc[j][3] - nm1); ls1 += sc[j][3];
        }
        ls0 += __shfl_xor_sync(0xffffffffu, ls0, 1);
        ls0 += __shfl_xor_sync(0xffffffffu, ls0, 2);
        ls1 += __shfl_xor_sync(0xffffffffu, ls1, 1);
        ls1 += __shfl_xor_sync(0xffffffffu, ls1, 2);
        l0 = l0 * a0 + ls0;
        l1 = l1 * a1 + ls1;
        m0 = nm0; m1 = nm1;
#pragma unroll
        for (int j = 0; j < 8; j++) {
            O[j][0] *= a0; O[j][1] *= a0;
            O[j][2] *= a1; O[j][3] *= a1;
        }

        // ---- O += P V ----
#pragma unroll
        for (int t = 0; t < 2; t++) {
            unsigned ph[4], pl[4];
            split_pair(sc[2*t][0],   sc[2*t][1],   ph[0], pl[0]);
            split_pair(sc[2*t][2],   sc[2*t][3],   ph[1], pl[1]);
            split_pair(sc[2*t+1][0], sc[2*t+1][1], ph[2], pl[2]);
            split_pair(sc[2*t+1][2], sc[2*t+1][3], ph[3], pl[3]);
            int rr = 16 * t + ((grp & 1) << 3) + li;
            int r7 = rr & 7;
#pragma unroll
            for (int jp = 0; jp < 4; jp++) {
                int sw = (((2 * jp + (grp >> 1)) ^ r7) << 4);
                unsigned h0, h1, h2, h3, e0, e1, e2, e3;
                ldsm4t(h0, h1, h2, h3, S + 8192  + rr * 128 + sw);
                ldsm4t(e0, e1, e2, e3, S + 12288 + rr * 128 + sw);
                mma4(O[2*jp],   ph, h0, h1);
                mma4(O[2*jp],   pl, h0, h1);
                mma4(O[2*jp],   ph, e0, e1);
                mma4(O[2*jp+1], ph, h2, h3);
                mma4(O[2*jp+1], pl, h2, h3);
                mma4(O[2*jp+1], ph, e2, e3);
            }
        }
        __syncthreads();
    }

    // ---- normalize + write ----
    float inv0 = 1.f / l0, inv1 = 1.f / l1;
    int tok0 = b * THW + qr0 + mw + g;
#pragma unroll
    for (int j = 0; j < 8; j++) {
        int col = h * DA + j * 8 + 2 * tg;
        unsigned hi, lo;
        split_pair(O[j][0] * inv0, O[j][1] * inv0, hi, lo);
        *(unsigned*)(g_aoh + (size_t)tok0 * DD + col) = hi;
        *(unsigned*)(g_aol + (size_t)tok0 * DD + col) = lo;
        split_pair(O[j][2] * inv1, O[j][3] * inv1, hi, lo);
        *(unsigned*)(g_aoh + (size_t)(tok0 + 8) * DD + col) = hi;
        *(unsigned*)(g_aol + (size_t)(tok0 + 8) * DD + col) = lo;
    }
}

// ---------------------------------------------------------------- launch
extern "C" void kernel_launch(void* const* d_in, const int* in_sizes, int n_in,
                              void* d_out, int out_size) {
    const float* x     = (const float*)d_in[0];
    const float* Bb    = (const float*)d_in[1];
    const int*   M     = (const int*)  d_in[2];
    const float* gamma = (const float*)d_in[3];
    const float* beta  = (const float*)d_in[4];
    const float* wq    = (const float*)d_in[5];
    const float* wk    = (const float*)d_in[6];
    const float* wv    = (const float*)d_in[7];
    const float* wp    = (const float*)d_in[8];
    float* out = (float*)d_out;

    cudaFuncSetAttribute(qkv_g,  cudaFuncAttributeMaxDynamicSharedMemorySize, 2 * STG);
    cudaFuncSetAttribute(proj_g, cudaFuncAttributeMaxDynamicSharedMemorySize, 2 * STG);

    ln_kernel<<<NROWS, 128>>>(x, gamma, beta);
    prep_w<<<24, 256>>>(wq, wk, wv);
    prep_wp<<<512, 256>>>(wp);
    qkv_g<<<dim3(NROWS / 128, NQKV / 64), 256, 2 * STG>>>();
    attn_kernel<<<dim3(THW / 128, NA * BSZ), 256>>>(Bb, M);
    proj_g<<<dim3(NROWS / 128, DD / 64), 256, 2 * STG>>>(x, out);
}

// round 11
// speedup vs baseline: 1.1823x; 1.1823x over previous
#include <cuda_runtime.h>
#include <cuda_fp16.h>

#define NA   8
#define BSZ  4
#define THW  1024
#define DD   512
#define DA   64
#define NROWS (BSZ*THW)   // 4096
#define NQKV (3*NA*DA)    // 1536
#define STG  40960        // GEMM stage: Ah16K | Al16K | B8K

// ---------------- device scratch (allocation forbidden) ----------------
__device__ __half g_xh[NROWS*DD], g_xl[NROWS*DD];          // normalized x hi/lo
__device__ __half g_qh[NA*NROWS*DA], g_ql[NA*NROWS*DA];    // q (pre-scaled 1/8) hi/lo
__device__ __half g_k [NA*NROWS*DA];                       // k single fp16
__device__ __half g_v [NA*NROWS*DA];                       // v single fp16
__device__ __half g_aoh[NROWS*DD], g_aol[NROWS*DD];        // concat attn out hi/lo
__device__ __half g_wt[NQKV*DD];                           // qkv weights [n][d] fp16
__device__ __half g_wp[DD*DD];                             // proj weights [o][i] fp16

// ---------------- helpers ----------------
__device__ __forceinline__ void mma4(float c[4], const unsigned a[4], unsigned b0, unsigned b1) {
    asm volatile(
        "mma.sync.aligned.m16n8k16.row.col.f32.f16.f16.f32 "
        "{%0,%1,%2,%3}, {%4,%5,%6,%7}, {%8,%9}, {%0,%1,%2,%3};\n"
        : "+f"(c[0]), "+f"(c[1]), "+f"(c[2]), "+f"(c[3])
        : "r"(a[0]), "r"(a[1]), "r"(a[2]), "r"(a[3]), "r"(b0), "r"(b1));
}

__device__ __forceinline__ void ldsm4(unsigned& r0, unsigned& r1, unsigned& r2, unsigned& r3,
                                      const void* p) {
    unsigned addr = (unsigned)__cvta_generic_to_shared(p);
    asm volatile("ldmatrix.sync.aligned.m8n8.x4.shared.b16 {%0,%1,%2,%3}, [%4];"
                 : "=r"(r0), "=r"(r1), "=r"(r2), "=r"(r3) : "r"(addr));
}

__device__ __forceinline__ void ldsm4t(unsigned& r0, unsigned& r1, unsigned& r2, unsigned& r3,
                                       const void* p) {
    unsigned addr = (unsigned)__cvta_generic_to_shared(p);
    asm volatile("ldmatrix.sync.aligned.m8n8.x4.trans.shared.b16 {%0,%1,%2,%3}, [%4];"
                 : "=r"(r0), "=r"(r1), "=r"(r2), "=r"(r3) : "r"(addr));
}

__device__ __forceinline__ void cpa16(void* dst, const void* src) {
    unsigned d = (unsigned)__cvta_generic_to_shared(dst);
    asm volatile("cp.async.cg.shared.global [%0], [%1], 16;" :: "r"(d), "l"(src));
}
__device__ __forceinline__ void cp_commit() {
    asm volatile("cp.async.commit_group;" ::: "memory");
}
template<int N> __device__ __forceinline__ void cp_wait() {
    asm volatile("cp.async.wait_group %0;" :: "n"(N) : "memory");
}

__device__ __forceinline__ void split1(float x, __half& h, __half& l) {
    h = __float2half_rn(x);
    l = __float2half_rn(x - __half2float(h));
}

// pack two floats -> (hi half2, lo half2) as raw u32
__device__ __forceinline__ void split_pair(float a, float b, unsigned& hi, unsigned& lo) {
    __half ah = __float2half_rn(a), bh = __float2half_rn(b);
    float ar = a - __half2float(ah), br = b - __half2float(bh);
    __half2 h2; h2.x = ah; h2.y = bh;
    __half2 l2; l2.x = __float2half_rn(ar); l2.y = __float2half_rn(br);
    hi = *reinterpret_cast<unsigned*>(&h2);
    lo = *reinterpret_cast<unsigned*>(&l2);
}

__device__ __forceinline__ unsigned pack2(float a, float b) {
    __half2 h2; h2.x = __float2half_rn(a); h2.y = __float2half_rn(b);
    return *reinterpret_cast<unsigned*>(&h2);
}

// ---------------------------------------------------------------- LayerNorm
__global__ void ln_kernel(const float* __restrict__ x,
                          const float* __restrict__ gamma,
                          const float* __restrict__ beta) {
    int row = blockIdx.x;
    int t   = threadIdx.x;              // 128 threads
    const float* xr = x + (size_t)row * DD;
    float v[4];
    float s = 0.f;
#pragma unroll
    for (int i = 0; i < 4; i++) { v[i] = xr[i * 128 + t]; s += v[i]; }

    __shared__ float rbuf[4];
    __shared__ float stat;
#pragma unroll
    for (int o = 16; o > 0; o >>= 1) s += __shfl_xor_sync(0xffffffffu, s, o);
    if ((t & 31) == 0) rbuf[t >> 5] = s;
    __syncthreads();
    if (t == 0) stat = rbuf[0] + rbuf[1] + rbuf[2] + rbuf[3];
    __syncthreads();
    float mean = stat * (1.f / DD);

    float ss = 0.f;
#pragma unroll
    for (int i = 0; i < 4; i++) { float d = v[i] - mean; ss += d * d; }
    __syncthreads();
#pragma unroll
    for (int o = 16; o > 0; o >>= 1) ss += __shfl_xor_sync(0xffffffffu, ss, o);
    if ((t & 31) == 0) rbuf[t >> 5] = ss;
    __syncthreads();
    if (t == 0) stat = rbuf[0] + rbuf[1] + rbuf[2] + rbuf[3];
    __syncthreads();
    float rstd = rsqrtf(stat * (1.f / DD) + 1e-5f);

#pragma unroll
    for (int i = 0; i < 4; i++) {
        int c = i * 128 + t;
        float y = (v[i] - mean) * rstd * gamma[c] + beta[c];
        __half h, l; split1(y, h, l);
        g_xh[(size_t)row * DD + c] = h;
        g_xl[(size_t)row * DD + c] = l;
    }
}

// ------------------------------------------------- weight prep (smem transpose)
// Wt[n][d], n = which*512 + h*64 + e, single fp16.  24 blocks x 256 thr.
__global__ void prep_w(const float* __restrict__ wq,
                       const float* __restrict__ wk,
                       const float* __restrict__ wv) {
    __shared__ float tile[64][65];
    int which = blockIdx.x >> 3, h = blockIdx.x & 7;
    const float* w = ((which == 0) ? wq : (which == 1) ? wk : wv) + (size_t)h * DD * DA;
    int n0 = which * 512 + h * 64;

    for (int d0 = 0; d0 < DD; d0 += 64) {
#pragma unroll
        for (int it = 0; it < 16; it++) {
            int idx = it * 256 + threadIdx.x;    // 4096
            int r = idx >> 6, e = idx & 63;
            tile[r][e] = w[(size_t)(d0 + r) * DA + e];
        }
        __syncthreads();
#pragma unroll
        for (int it = 0; it < 8; it++) {
            int idx = it * 256 + threadIdx.x;    // 2048
            int e = idx >> 5, j = idx & 31;
            *(unsigned*)(g_wt + (size_t)(n0 + e) * DD + d0 + 2 * j) =
                pack2(tile[2 * j][e], tile[2 * j + 1][e]);
        }
        __syncthreads();
    }
}

__global__ void prep_wp(const float* __restrict__ wp) {
    size_t p = (size_t)blockIdx.x * 256 + threadIdx.x;   // grid 512
    float2 v = ((const float2*)wp)[p];
    ((unsigned*)g_wp)[p] = pack2(v.x, v.y);
}

// ---------------------------------------------------------------- big GEMM
// C[128m x 64n] per block, 8 warps (4m x 2n), warp 32x32, k-tile 64.
// Double-buffered cp.async, 2 stages x 40KB dynamic smem.
// A = hi/lo fp16 split, B = single fp16.
struct GemmAcc { float c[2][4][4]; };

__device__ __forceinline__ void gemm_stage_load(
    const __half* Ah_src, const __half* Al_src, const __half* Bsrc,
    char* S, int tid, int k0)
{
#pragma unroll
    for (int it = 0; it < 4; it++) {
        int flat = it * 256 + tid;
        int r = flat >> 3, cc = flat & 7;
        size_t so = (size_t)r * DD + k0 + cc * 8;
        int off = r * 128 + ((cc ^ (r & 7)) << 4);
        cpa16(S + off,         Ah_src + so);
        cpa16(S + 16384 + off, Al_src + so);
    }
#pragma unroll
    for (int it = 0; it < 2; it++) {
        int flat = it * 256 + tid;
        int r = flat >> 3, cc = flat & 7;
        size_t so = (size_t)r * DD + k0 + cc * 8;
        int off = r * 128 + ((cc ^ (r & 7)) << 4);
        cpa16(S + 32768 + off, Bsrc + so);
    }
    cp_commit();
}

__device__ __forceinline__ void gemm_stage_compute(
    char* S, int mw, int nw, int grp, int li, GemmAcc& acc)
{
    char* Ah = S;
    char* Al = S + 16384;
    char* Bs = S + 32768;
#pragma unroll
    for (int s4 = 0; s4 < 4; s4++) {
        unsigned afh[2][4], afl[2][4];
#pragma unroll
        for (int mi = 0; mi < 2; mi++) {
            int ar = mw + mi * 16 + ((grp & 1) << 3) + li;
            int sw = (((s4 * 2 + (grp >> 1)) ^ (ar & 7)) << 4);
            ldsm4(afh[mi][0], afh[mi][1], afh[mi][2], afh[mi][3], Ah + ar * 128 + sw);
            ldsm4(afl[mi][0], afl[mi][1], afl[mi][2], afl[mi][3], Al + ar * 128 + sw);
        }
        unsigned bf[2][4];
#pragma unroll
        for (int jp = 0; jp < 2; jp++) {
            int br = nw + jp * 16 + ((grp >> 1) << 3) + li;
            int sw = (((s4 * 2 + (grp & 1)) ^ (br & 7)) << 4);
            ldsm4(bf[jp][0], bf[jp][1], bf[jp][2], bf[jp][3], Bs + br * 128 + sw);
        }
#pragma unroll
        for (int mi = 0; mi < 2; mi++)
#pragma unroll
            for (int jp = 0; jp < 2; jp++) {
                float* c0 = acc.c[mi][jp * 2];
                float* c1 = acc.c[mi][jp * 2 + 1];
                mma4(c0, afh[mi], bf[jp][0], bf[jp][1]);
                mma4(c0, afl[mi], bf[jp][0], bf[jp][1]);
                mma4(c1, afh[mi], bf[jp][2], bf[jp][3]);
                mma4(c1, afl[mi], bf[jp][2], bf[jp][3]);
            }
    }
}

__device__ __forceinline__ void gemm_mainloop(
    const __half* Ah_src, const __half* Al_src, const __half* Bsrc,
    char* sm, int tid, int mw, int nw, int grp, int li, GemmAcc& acc)
{
    gemm_stage_load(Ah_src, Al_src, Bsrc, sm, tid, 0);
    const int NK = DD / 64;   // 8
#pragma unroll 1
    for (int kt = 0; kt < NK; kt++) {
        if (kt < NK - 1) {
            gemm_stage_load(Ah_src, Al_src, Bsrc,
                            sm + ((kt + 1) & 1) * STG, tid, (kt + 1) * 64);
            cp_wait<1>();
        } else {
            cp_wait<0>();
        }
        __syncthreads();
        gemm_stage_compute(sm + (kt & 1) * STG, mw, nw, grp, li, acc);
        __syncthreads();
    }
}

// qkv GEMM: grid (4096/128, 1536/64), 256 thr, dynamic smem 80KB
__global__ __launch_bounds__(256, 2) void qkv_g() {
    extern __shared__ __align__(16) char smd[];
    int m0 = blockIdx.x * 128, n0 = blockIdx.y * 64;
    int which = n0 >> 9, h = (n0 >> 6) & 7;

    int tid = threadIdx.x, lane = tid & 31, wid = tid >> 5;
    int g = lane >> 2, tg = lane & 3, grp = lane >> 3, li = lane & 7;
    int mw = (wid >> 1) * 32, nw = (wid & 1) * 32;

    GemmAcc acc = {};
    gemm_mainloop(g_xh + (size_t)m0 * DD, g_xl + (size_t)m0 * DD,
                  g_wt + (size_t)n0 * DD, smd, tid, mw, nw, grp, li, acc);

#pragma unroll
    for (int mi = 0; mi < 2; mi++)
#pragma unroll
        for (int nj = 0; nj < 4; nj++) {
            int m = m0 + mw + mi * 16 + g;
            int e = nw + nj * 8 + 2 * tg;
            size_t b0 = ((size_t)(h * NROWS + m)) * DA + e;
            size_t b1 = ((size_t)(h * NROWS + m + 8)) * DA + e;
            if (which == 0) {
                unsigned hi, lo;
                split_pair(acc.c[mi][nj][0] * 0.125f, acc.c[mi][nj][1] * 0.125f, hi, lo);
                *(unsigned*)(g_qh + b0) = hi; *(unsigned*)(g_ql + b0) = lo;
                split_pair(acc.c[mi][nj][2] * 0.125f, acc.c[mi][nj][3] * 0.125f, hi, lo);
                *(unsigned*)(g_qh + b1) = hi; *(unsigned*)(g_ql + b1) = lo;
            } else {
                __half* o = (which == 1) ? g_k : g_v;
                *(unsigned*)(o + b0) = pack2(acc.c[mi][nj][0], acc.c[mi][nj][1]);
                *(unsigned*)(o + b1) = pack2(acc.c[mi][nj][2], acc.c[mi][nj][3]);
            }
        }
}

// proj GEMM + residual: grid (4096/128, 512/64), 256 thr, dynamic smem 80KB
__global__ __launch_bounds__(256, 2) void proj_g(const float* __restrict__ x,
                                                 float* __restrict__ out) {
    extern __shared__ __align__(16) char smd[];
    int m0 = blockIdx.x * 128, n0 = blockIdx.y * 64;

    int tid = threadIdx.x, lane = tid & 31, wid = tid >> 5;
    int g = lane >> 2, tg = lane & 3, grp = lane >> 3, li = lane & 7;
    int mw = (wid >> 1) * 32, nw = (wid & 1) * 32;

    GemmAcc acc = {};
    gemm_mainloop(g_aoh + (size_t)m0 * DD, g_aol + (size_t)m0 * DD,
                  g_wp + (size_t)n0 * DD, smd, tid, mw, nw, grp, li, acc);

#pragma unroll
    for (int mi = 0; mi < 2; mi++)
#pragma unroll
        for (int nj = 0; nj < 4; nj++) {
            int m = m0 + mw + mi * 16 + g;
            int n = n0 + nw + nj * 8 + 2 * tg;
#pragma unroll
            for (int rr = 0; rr < 2; rr++) {
                size_t off = (size_t)(m + rr * 8) * DD + n;
                float2 xr = *(const float2*)&x[off];
                float2 r;
                r.x = acc.c[mi][nj][rr * 2 + 0] + xr.x;
                r.y = acc.c[mi][nj][rr * 2 + 1] + xr.y;
                *(float2*)&out[off] = r;
            }
        }
}

// ---------------------------------------------------------------- fused attention
// grid (THW/128, NA*BSZ), 256 threads (8 warps, m16 each). k-tile = 32 tokens,
// double-buffered stages of 8KB (K 4K | V 4K). K,V single fp16; Q/P hi-lo split.
__global__ __launch_bounds__(256) void attn_kernel(const float* __restrict__ Bb,
                                                   const int* __restrict__ M) {
    __shared__ __align__(16) char sm[2][16384];

    int hb = blockIdx.y;
    int h = hb >> 2, b = hb & 3;
    int qr0 = blockIdx.x * 128;

    int tid = threadIdx.x, lane = tid & 31, wid = tid >> 5;
    int g = lane >> 2, tg = lane & 3, grp = lane >> 3, li = lane & 7;
    int mw = wid * 16;

    size_t kv = (size_t)(h * NROWS + b * THW) * DA;

    // ---- Q tile into sm[0](hi)/sm[1](lo), extract frags ----
#pragma unroll
    for (int it = 0; it < 4; it++) {
        int flat = it * 256 + tid;
        int r = flat >> 3, cc = flat & 7;
        size_t so = kv + (size_t)(qr0 + r) * DA + cc * 8;
        int off = r * 128 + ((cc ^ (r & 7)) << 4);
        cpa16(sm[0] + off, g_qh + so);
        cpa16(sm[1] + off, g_ql + so);
    }
    cp_commit();
    cp_wait<0>();
    __syncthreads();

    unsigned qfh[4][4], qfl[4][4];
    {
        int qrow = mw + ((grp & 1) << 3) + li;
        int q7 = qrow & 7;
#pragma unroll
        for (int s4 = 0; s4 < 4; s4++) {
            int sw = (((s4 * 2 + (grp >> 1)) ^ q7) << 4);
            ldsm4(qfh[s4][0], qfh[s4][1], qfh[s4][2], qfh[s4][3], sm[0] + qrow * 128 + sw);
            ldsm4(qfl[s4][0], qfl[s4][1], qfl[s4][2], qfl[s4][3], sm[1] + qrow * 128 + sw);
        }
    }
    __syncthreads();

    // prefetch stage 0 (K at +0, V at +4096; 32 rows x 8 chunks, 1 cpa each)
    {
        int r = tid >> 3, cc = tid & 7;
        size_t so = kv + (size_t)r * DA + cc * 8;
        int off = r * 128 + ((cc ^ (r & 7)) << 4);
        cpa16(sm[0] + off,        g_k + so);
        cpa16(sm[0] + 4096 + off, g_v + so);
        cp_commit();
    }

    float m0 = -1e30f, m1 = -1e30f, l0 = 0.f, l1 = 0.f;
    float O[8][4] = {};

    const float* Brow = Bb + ((size_t)hb * THW + (qr0 + mw + g)) * THW + 2 * tg;
    const int*   Mrow = M  + (size_t)(qr0 + mw + g) * THW + 2 * tg;

    int pr = tid >> 3, pc = tid & 7;
    int poff = pr * 128 + ((pc ^ (pr & 7)) << 4);

    for (int kt = 0; kt < 32; kt++) {
        if (kt < 31) {
            char* S = sm[(kt + 1) & 1];
            size_t so = kv + (size_t)((kt + 1) * 32 + pr) * DA + pc * 8;
            cpa16(S + poff,        g_k + so);
            cpa16(S + 4096 + poff, g_v + so);
            cp_commit();
            cp_wait<1>();
        } else {
            cp_wait<0>();
        }
        __syncthreads();
        char* S = sm[kt & 1];

        // ---- S = Q K^T (2-MMA split), 32 kcols -> sc[4][4] ----
        float sc[4][4] = {};
#pragma unroll
        for (int s4 = 0; s4 < 4; s4++) {
#pragma unroll
            for (int jp = 0; jp < 2; jp++) {
                int rr = jp * 16 + ((grp >> 1) << 3) + li;
                int sw = (((s4 * 2 + (grp & 1)) ^ (rr & 7)) << 4);
                unsigned k0, k1, k2, k3;
                ldsm4(k0, k1, k2, k3, S + rr * 128 + sw);
                mma4(sc[2*jp],   qfh[s4], k0, k1);
                mma4(sc[2*jp],   qfl[s4], k0, k1);
                mma4(sc[2*jp+1], qfh[s4], k2, k3);
                mma4(sc[2*jp+1], qfl[s4], k2, k3);
            }
        }

        // ---- bias + mask ----
        const float* Bp = Brow + kt * 32;
        const int*   Mp = Mrow + kt * 32;
#pragma unroll
        for (int j = 0; j < 4; j++) {
            float2 b0 = *(const float2*)(Bp + j * 8);
            int2   i0 = *(const int2*)  (Mp + j * 8);
            sc[j][0] = i0.x ? -10000.f : sc[j][0] + b0.x;
            sc[j][1] = i0.y ? -10000.f : sc[j][1] + b0.y;
            float2 b1 = *(const float2*)(Bp + 8 * THW + j * 8);
            int2   i1 = *(const int2*)  (Mp + 8 * THW + j * 8);
            sc[j][2] = i1.x ? -10000.f : sc[j][2] + b1.x;
            sc[j][3] = i1.y ? -10000.f : sc[j][3] + b1.y;
        }

        // ---- online softmax ----
        float rm0 = -1e30f, rm1 = -1e30f;
#pragma unroll
        for (int j = 0; j < 4; j++) {
            rm0 = fmaxf(rm0, fmaxf(sc[j][0], sc[j][1]));
            rm1 = fmaxf(rm1, fmaxf(sc[j][2], sc[j][3]));
        }
        rm0 = fmaxf(rm0, __shfl_xor_sync(0xffffffffu, rm0, 1));
        rm0 = fmaxf(rm0, __shfl_xor_sync(0xffffffffu, rm0, 2));
        rm1 = fmaxf(rm1, __shfl_xor_sync(0xffffffffu, rm1, 1));
        rm1 = fmaxf(rm1, __shfl_xor_sync(0xffffffffu, rm1, 2));
        float nm0 = fmaxf(m0, rm0), nm1 = fmaxf(m1, rm1);
        float a0 = __expf(m0 - nm0), a1 = __expf(m1 - nm1);
        float ls0 = 0.f, ls1 = 0.f;
#pragma unroll
        for (int j = 0; j < 4; j++) {
            sc[j][0] = __expf(sc[j][0] - nm0); ls0 += sc[j][0];
            sc[j][1] = __expf(sc[j][1] - nm0); ls0 += sc[j][1];
            sc[j][2] = __expf(sc[j][2] - nm1); ls1 += sc[j][2];
            sc[j][3] = __expf(sc[j][3] - nm1); ls1 += sc[j][3];
        }
        ls0 += __shfl_xor_sync(0xffffffffu, ls0, 1);
        ls0 += __shfl_xor_sync(0xffffffffu, ls0, 2);
        ls1 += __shfl_xor_sync(0xffffffffu, ls1, 1);
        ls1 += __shfl_xor_sync(0xffffffffu, ls1, 2);
        l0 = l0 * a0 + ls0;
        l1 = l1 * a1 + ls1;
        m0 = nm0; m1 = nm1;
#pragma unroll
        for (int j = 0; j < 8; j++) {
            O[j][0] *= a0; O[j][1] *= a0;
            O[j][2] *= a1; O[j][3] *= a1;
        }

        // ---- O += P V (P hi/lo from regs, V single) ----
#pragma unroll
        for (int t = 0; t < 2; t++) {
            unsigned ph[4], pl[4];
            split_pair(sc[2*t][0],   sc[2*t][1],   ph[0], pl[0]);
            split_pair(sc[2*t][2],   sc[2*t][3],   ph[1], pl[1]);
            split_pair(sc[2*t+1][0], sc[2*t+1][1], ph[2], pl[2]);
            split_pair(sc[2*t+1][2], sc[2*t+1][3], ph[3], pl[3]);
            int rr = 16 * t + ((grp & 1) << 3) + li;
            int r7 = rr & 7;
#pragma unroll
            for (int jp = 0; jp < 4; jp++) {
                int sw = (((2 * jp + (grp >> 1)) ^ r7) << 4);
                unsigned v0, v1, v2, v3;
                ldsm4t(v0, v1, v2, v3, S + 4096 + rr * 128 + sw);
                mma4(O[2*jp],   ph, v0, v1);
                mma4(O[2*jp],   pl, v0, v1);
                mma4(O[2*jp+1], ph, v2, v3);
                mma4(O[2*jp+1], pl, v2, v3);
            }
        }
        __syncthreads();
    }

    // ---- normalize + write (fp16 hi/lo for proj) ----
    float inv0 = 1.f / l0, inv1 = 1.f / l1;
    int tok0 = b * THW + qr0 + mw + g;
#pragma unroll
    for (int j = 0; j < 8; j++) {
        int col = h * DA + j * 8 + 2 * tg;
        unsigned hi, lo;
        split_pair(O[j][0] * inv0, O[j][1] * inv0, hi, lo);
        *(unsigned*)(g_aoh + (size_t)tok0 * DD + col) = hi;
        *(unsigned*)(g_aol + (size_t)tok0 * DD + col) = lo;
        split_pair(O[j][2] * inv1, O[j][3] * inv1, hi, lo);
        *(unsigned*)(g_aoh + (size_t)(tok0 + 8) * DD + col) = hi;
        *(unsigned*)(g_aol + (size_t)(tok0 + 8) * DD + col) = lo;
    }
}

// ---------------------------------------------------------------- launch
extern "C" void kernel_launch(void* const* d_in, const int* in_sizes, int n_in,
                              void* d_out, int out_size) {
    const float* x     = (const float*)d_in[0];
    const float* Bb    = (const float*)d_in[1];
    const int*   M     = (const int*)  d_in[2];
    const float* gamma = (const float*)d_in[3];
    const float* beta  = (const float*)d_in[4];
    const float* wq    = (const float*)d_in[5];
    const float* wk    = (const float*)d_in[6];
    const float* wv    = (const float*)d_in[7];
    const float* wp    = (const float*)d_in[8];
    float* out = (float*)d_out;

    cudaFuncSetAttribute(qkv_g,  cudaFuncAttributeMaxDynamicSharedMemorySize, 2 * STG);
    cudaFuncSetAttribute(proj_g, cudaFuncAttributeMaxDynamicSharedMemorySize, 2 * STG);

    ln_kernel<<<NROWS, 128>>>(x, gamma, beta);
    prep_w<<<24, 256>>>(wq, wk, wv);
    prep_wp<<<512, 256>>>(wp);
    qkv_g<<<dim3(NROWS / 128, NQKV / 64), 256, 2 * STG>>>();
    attn_kernel<<<dim3(THW / 128, NA * BSZ), 256>>>(Bb, M);
    proj_g<<<dim3(NROWS / 128, DD / 64), 256, 2 * STG>>>(x, out);
}

// round 12
// speedup vs baseline: 1.2605x; 1.0662x over previous
#include <cuda_runtime.h>
#include <cuda_fp16.h>

#define NA   8
#define BSZ  4
#define THW  1024
#define DD   512
#define DA   64
#define NROWS (BSZ*THW)   // 4096
#define NQKV (3*NA*DA)    // 1536
#define STG  24576        // GEMM stage: A 16K | B 8K

// ---------------- device scratch (allocation forbidden) ----------------
__device__ __half g_x [NROWS*DD];                // normalized x, fp16
__device__ __half g_q [NA*NROWS*DA];             // q (pre-scaled 1/8)
__device__ __half g_k [NA*NROWS*DA];
__device__ __half g_v [NA*NROWS*DA];
__device__ __half g_ao[NROWS*DD];                // concat attn out
__device__ __half g_wt[NQKV*DD];                 // qkv weights [n][d]
__device__ __half g_wp[DD*DD];                   // proj weights [o][i]

// ---------------- helpers ----------------
__device__ __forceinline__ void mma4(float c[4], const unsigned a[4], unsigned b0, unsigned b1) {
    asm volatile(
        "mma.sync.aligned.m16n8k16.row.col.f32.f16.f16.f32 "
        "{%0,%1,%2,%3}, {%4,%5,%6,%7}, {%8,%9}, {%0,%1,%2,%3};\n"
        : "+f"(c[0]), "+f"(c[1]), "+f"(c[2]), "+f"(c[3])
        : "r"(a[0]), "r"(a[1]), "r"(a[2]), "r"(a[3]), "r"(b0), "r"(b1));
}

__device__ __forceinline__ void ldsm4(unsigned& r0, unsigned& r1, unsigned& r2, unsigned& r3,
                                      const void* p) {
    unsigned addr = (unsigned)__cvta_generic_to_shared(p);
    asm volatile("ldmatrix.sync.aligned.m8n8.x4.shared.b16 {%0,%1,%2,%3}, [%4];"
                 : "=r"(r0), "=r"(r1), "=r"(r2), "=r"(r3) : "r"(addr));
}

__device__ __forceinline__ void ldsm4t(unsigned& r0, unsigned& r1, unsigned& r2, unsigned& r3,
                                       const void* p) {
    unsigned addr = (unsigned)__cvta_generic_to_shared(p);
    asm volatile("ldmatrix.sync.aligned.m8n8.x4.trans.shared.b16 {%0,%1,%2,%3}, [%4];"
                 : "=r"(r0), "=r"(r1), "=r"(r2), "=r"(r3) : "r"(addr));
}

__device__ __forceinline__ void cpa16(void* dst, const void* src) {
    unsigned d = (unsigned)__cvta_generic_to_shared(dst);
    asm volatile("cp.async.cg.shared.global [%0], [%1], 16;" :: "r"(d), "l"(src));
}
__device__ __forceinline__ void cp_commit() {
    asm volatile("cp.async.commit_group;" ::: "memory");
}
template<int N> __device__ __forceinline__ void cp_wait() {
    asm volatile("cp.async.wait_group %0;" :: "n"(N) : "memory");
}

__device__ __forceinline__ unsigned pack2(float a, float b) {
    __half2 h2; h2.x = __float2half_rn(a); h2.y = __float2half_rn(b);
    return *reinterpret_cast<unsigned*>(&h2);
}

// ---------------------------------------------------------------- LayerNorm
__global__ void ln_kernel(const float* __restrict__ x,
                          const float* __restrict__ gamma,
                          const float* __restrict__ beta) {
    int row = blockIdx.x;
    int t   = threadIdx.x;              // 128 threads
    const float* xr = x + (size_t)row * DD;
    float v[4];
    float s = 0.f;
#pragma unroll
    for (int i = 0; i < 4; i++) { v[i] = xr[i * 128 + t]; s += v[i]; }

    __shared__ float rbuf[4];
    __shared__ float stat;
#pragma unroll
    for (int o = 16; o > 0; o >>= 1) s += __shfl_xor_sync(0xffffffffu, s, o);
    if ((t & 31) == 0) rbuf[t >> 5] = s;
    __syncthreads();
    if (t == 0) stat = rbuf[0] + rbuf[1] + rbuf[2] + rbuf[3];
    __syncthreads();
    float mean = stat * (1.f / DD);

    float ss = 0.f;
#pragma unroll
    for (int i = 0; i < 4; i++) { float d = v[i] - mean; ss += d * d; }
    __syncthreads();
#pragma unroll
    for (int o = 16; o > 0; o >>= 1) ss += __shfl_xor_sync(0xffffffffu, ss, o);
    if ((t & 31) == 0) rbuf[t >> 5] = ss;
    __syncthreads();
    if (t == 0) stat = rbuf[0] + rbuf[1] + rbuf[2] + rbuf[3];
    __syncthreads();
    float rstd = rsqrtf(stat * (1.f / DD) + 1e-5f);

#pragma unroll
    for (int i = 0; i < 4; i++) {
        int c = i * 128 + t;
        float y = (v[i] - mean) * rstd * gamma[c] + beta[c];
        g_x[(size_t)row * DD + c] = __float2half_rn(y);
    }
}

// ------------------------------------------------- weight prep (smem transpose)
__global__ void prep_w(const float* __restrict__ wq,
                       const float* __restrict__ wk,
                       const float* __restrict__ wv) {
    __shared__ float tile[64][65];
    int which = blockIdx.x >> 3, h = blockIdx.x & 7;
    const float* w = ((which == 0) ? wq : (which == 1) ? wk : wv) + (size_t)h * DD * DA;
    int n0 = which * 512 + h * 64;

    for (int d0 = 0; d0 < DD; d0 += 64) {
#pragma unroll
        for (int it = 0; it < 16; it++) {
            int idx = it * 256 + threadIdx.x;    // 4096
            int r = idx >> 6, e = idx & 63;
            tile[r][e] = w[(size_t)(d0 + r) * DA + e];
        }
        __syncthreads();
#pragma unroll
        for (int it = 0; it < 8; it++) {
            int idx = it * 256 + threadIdx.x;    // 2048
            int e = idx >> 5, j = idx & 31;
            *(unsigned*)(g_wt + (size_t)(n0 + e) * DD + d0 + 2 * j) =
                pack2(tile[2 * j][e], tile[2 * j + 1][e]);
        }
        __syncthreads();
    }
}

__global__ void prep_wp(const float* __restrict__ wp) {
    size_t p = (size_t)blockIdx.x * 256 + threadIdx.x;   // grid 512
    float2 v = ((const float2*)wp)[p];
    ((unsigned*)g_wp)[p] = pack2(v.x, v.y);
}

// ---------------------------------------------------------------- big GEMM
// C[128m x 64n] per block, 8 warps (4m x 2n), warp 32x32, k-tile 64.
// 3-stage cp.async pipeline, stages of 24KB (A 16K | B 8K) dynamic smem.
struct GemmAcc { float c[2][4][4]; };

__device__ __forceinline__ void gemm_stage_load(
    const __half* Asrc, const __half* Bsrc, char* S, int tid, int k0)
{
#pragma unroll
    for (int it = 0; it < 4; it++) {
        int flat = it * 256 + tid;
        int r = flat >> 3, cc = flat & 7;
        size_t so = (size_t)r * DD + k0 + cc * 8;
        int off = r * 128 + ((cc ^ (r & 7)) << 4);
        cpa16(S + off, Asrc + so);
    }
#pragma unroll
    for (int it = 0; it < 2; it++) {
        int flat = it * 256 + tid;
        int r = flat >> 3, cc = flat & 7;
        size_t so = (size_t)r * DD + k0 + cc * 8;
        int off = r * 128 + ((cc ^ (r & 7)) << 4);
        cpa16(S + 16384 + off, Bsrc + so);
    }
    cp_commit();
}

__device__ __forceinline__ void gemm_stage_compute(
    char* S, int mw, int nw, int grp, int li, GemmAcc& acc)
{
    char* As = S;
    char* Bs = S + 16384;
#pragma unroll
    for (int s4 = 0; s4 < 4; s4++) {
        unsigned af[2][4];
#pragma unroll
        for (int mi = 0; mi < 2; mi++) {
            int ar = mw + mi * 16 + ((grp & 1) << 3) + li;
            int sw = (((s4 * 2 + (grp >> 1)) ^ (ar & 7)) << 4);
            ldsm4(af[mi][0], af[mi][1], af[mi][2], af[mi][3], As + ar * 128 + sw);
        }
        unsigned bf[2][4];
#pragma unroll
        for (int jp = 0; jp < 2; jp++) {
            int br = nw + jp * 16 + ((grp >> 1) << 3) + li;
            int sw = (((s4 * 2 + (grp & 1)) ^ (br & 7)) << 4);
            ldsm4(bf[jp][0], bf[jp][1], bf[jp][2], bf[jp][3], Bs + br * 128 + sw);
        }
#pragma unroll
        for (int mi = 0; mi < 2; mi++)
#pragma unroll
            for (int jp = 0; jp < 2; jp++) {
                mma4(acc.c[mi][jp * 2],     af[mi], bf[jp][0], bf[jp][1]);
                mma4(acc.c[mi][jp * 2 + 1], af[mi], bf[jp][2], bf[jp][3]);
            }
    }
}

__device__ __forceinline__ void gemm_mainloop(
    const __half* Asrc, const __half* Bsrc,
    char* sm, int tid, int mw, int nw, int grp, int li, GemmAcc& acc)
{
    const int NK = DD / 64;   // 8
    gemm_stage_load(Asrc, Bsrc, sm,       tid, 0);
    gemm_stage_load(Asrc, Bsrc, sm + STG, tid, 64);
#pragma unroll 1
    for (int kt = 0; kt < NK; kt++) {
        if (kt + 2 < NK) {
            gemm_stage_load(Asrc, Bsrc, sm + ((kt + 2) % 3) * STG, tid, (kt + 2) * 64);
            cp_wait<2>();
        } else if (kt + 1 < NK) {
            cp_wait<1>();
        } else {
            cp_wait<0>();
        }
        __syncthreads();
        gemm_stage_compute(sm + (kt % 3) * STG, mw, nw, grp, li, acc);
        __syncthreads();
    }
}

// qkv GEMM: grid (4096/128, 1536/64), 256 thr, dynamic smem 72KB
__global__ __launch_bounds__(256, 2) void qkv_g() {
    extern __shared__ __align__(16) char smd[];
    int m0 = blockIdx.x * 128, n0 = blockIdx.y * 64;
    int which = n0 >> 9, h = (n0 >> 6) & 7;

    int tid = threadIdx.x, lane = tid & 31, wid = tid >> 5;
    int g = lane >> 2, tg = lane & 3, grp = lane >> 3, li = lane & 7;
    int mw = (wid >> 1) * 32, nw = (wid & 1) * 32;

    GemmAcc acc = {};
    gemm_mainloop(g_x + (size_t)m0 * DD, g_wt + (size_t)n0 * DD,
                  smd, tid, mw, nw, grp, li, acc);

    float scale = (which == 0) ? 0.125f : 1.0f;
    __half* o = (which == 0) ? g_q : ((which == 1) ? g_k : g_v);
#pragma unroll
    for (int mi = 0; mi < 2; mi++)
#pragma unroll
        for (int nj = 0; nj < 4; nj++) {
            int m = m0 + mw + mi * 16 + g;
            int e = nw + nj * 8 + 2 * tg;
            size_t b0 = ((size_t)(h * NROWS + m)) * DA + e;
            size_t b1 = ((size_t)(h * NROWS + m + 8)) * DA + e;
            *(unsigned*)(o + b0) = pack2(acc.c[mi][nj][0] * scale, acc.c[mi][nj][1] * scale);
            *(unsigned*)(o + b1) = pack2(acc.c[mi][nj][2] * scale, acc.c[mi][nj][3] * scale);
        }
}

// proj GEMM + residual: grid (4096/128, 512/64), 256 thr, dynamic smem 72KB
__global__ __launch_bounds__(256, 2) void proj_g(const float* __restrict__ x,
                                                 float* __restrict__ out) {
    extern __shared__ __align__(16) char smd[];
    int m0 = blockIdx.x * 128, n0 = blockIdx.y * 64;

    int tid = threadIdx.x, lane = tid & 31, wid = tid >> 5;
    int g = lane >> 2, tg = lane & 3, grp = lane >> 3, li = lane & 7;
    int mw = (wid >> 1) * 32, nw = (wid & 1) * 32;

    GemmAcc acc = {};
    gemm_mainloop(g_ao + (size_t)m0 * DD, g_wp + (size_t)n0 * DD,
                  smd, tid, mw, nw, grp, li, acc);

#pragma unroll
    for (int mi = 0; mi < 2; mi++)
#pragma unroll
        for (int nj = 0; nj < 4; nj++) {
            int m = m0 + mw + mi * 16 + g;
            int n = n0 + nw + nj * 8 + 2 * tg;
#pragma unroll
            for (int rr = 0; rr < 2; rr++) {
                size_t off = (size_t)(m + rr * 8) * DD + n;
                float2 xr = *(const float2*)&x[off];
                float2 r;
                r.x = acc.c[mi][nj][rr * 2 + 0] + xr.x;
                r.y = acc.c[mi][nj][rr * 2 + 1] + xr.y;
                *(float2*)&out[off] = r;
            }
        }
}

// ---------------------------------------------------------------- fused attention
// grid (THW/128, NA*BSZ), 256 threads (8 warps, m16 each). k-tile = 32 tokens,
// double-buffered stages of 8KB (K 4K | V 4K). Everything single fp16.
__global__ __launch_bounds__(256) void attn_kernel(const float* __restrict__ Bb,
                                                   const int* __restrict__ M) {
    __shared__ __align__(16) char sm[2][16384];

    int hb = blockIdx.y;
    int h = hb >> 2, b = hb & 3;
    int qr0 = blockIdx.x * 128;

    int tid = threadIdx.x, lane = tid & 31, wid = tid >> 5;
    int g = lane >> 2, tg = lane & 3, grp = lane >> 3, li = lane & 7;
    int mw = wid * 16;

    size_t kv = (size_t)(h * NROWS + b * THW) * DA;

    // ---- Q tile into sm[0], extract frags ----
#pragma unroll
    for (int it = 0; it < 4; it++) {
        int flat = it * 256 + tid;
        int r = flat >> 3, cc = flat & 7;
        size_t so = kv + (size_t)(qr0 + r) * DA + cc * 8;
        int off = r * 128 + ((cc ^ (r & 7)) << 4);
        cpa16(sm[0] + off, g_q + so);
    }
    cp_commit();
    cp_wait<0>();
    __syncthreads();

    unsigned qf[4][4];
    {
        int qrow = mw + ((grp & 1) << 3) + li;
        int q7 = qrow & 7;
#pragma unroll
        for (int s4 = 0; s4 < 4; s4++) {
            int sw = (((s4 * 2 + (grp >> 1)) ^ q7) << 4);
            ldsm4(qf[s4][0], qf[s4][1], qf[s4][2], qf[s4][3], sm[0] + qrow * 128 + sw);
        }
    }
    __syncthreads();

    // prefetch stage 0 (K at +0, V at +4096)
    {
        int r = tid >> 3, cc = tid & 7;
        size_t so = kv + (size_t)r * DA + cc * 8;
        int off = r * 128 + ((cc ^ (r & 7)) << 4);
        cpa16(sm[0] + off,        g_k + so);
        cpa16(sm[0] + 4096 + off, g_v + so);
        cp_commit();
    }

    float m0 = -1e30f, m1 = -1e30f, l0 = 0.f, l1 = 0.f;
    float O[8][4] = {};

    const float* Brow = Bb + ((size_t)hb * THW + (qr0 + mw + g)) * THW + 2 * tg;
    const int*   Mrow = M  + (size_t)(qr0 + mw + g) * THW + 2 * tg;

    int pr = tid >> 3, pc = tid & 7;
    int poff = pr * 128 + ((pc ^ (pr & 7)) << 4);

    for (int kt = 0; kt < 32; kt++) {
        if (kt < 31) {
            char* S = sm[(kt + 1) & 1];
            size_t so = kv + (size_t)((kt + 1) * 32 + pr) * DA + pc * 8;
            cpa16(S + poff,        g_k + so);
            cpa16(S + 4096 + poff, g_v + so);
            cp_commit();
            cp_wait<1>();
        } else {
            cp_wait<0>();
        }
        __syncthreads();
        char* S = sm[kt & 1];

        // ---- S = Q K^T, 32 kcols -> sc[4][4] ----
        float sc[4][4] = {};
#pragma unroll
        for (int s4 = 0; s4 < 4; s4++) {
#pragma unroll
            for (int jp = 0; jp < 2; jp++) {
                int rr = jp * 16 + ((grp >> 1) << 3) + li;
                int sw = (((s4 * 2 + (grp & 1)) ^ (rr & 7)) << 4);
                unsigned k0, k1, k2, k3;
                ldsm4(k0, k1, k2, k3, S + rr * 128 + sw);
                mma4(sc[2*jp],   qf[s4], k0, k1);
                mma4(sc[2*jp+1], qf[s4], k2, k3);
            }
        }

        // ---- bias + mask ----
        const float* Bp = Brow + kt * 32;
        const int*   Mp = Mrow + kt * 32;
#pragma unroll
        for (int j = 0; j < 4; j++) {
            float2 b0 = *(const float2*)(Bp + j * 8);
            int2   i0 = *(const int2*)  (Mp + j * 8);
            sc[j][0] = i0.x ? -10000.f : sc[j][0] + b0.x;
            sc[j][1] = i0.y ? -10000.f : sc[j][1] + b0.y;
            float2 b1 = *(const float2*)(Bp + 8 * THW + j * 8);
            int2   i1 = *(const int2*)  (Mp + 8 * THW + j * 8);
            sc[j][2] = i1.x ? -10000.f : sc[j][2] + b1.x;
            sc[j][3] = i1.y ? -10000.f : sc[j][3] + b1.y;
        }

        // ---- online softmax ----
        float rm0 = -1e30f, rm1 = -1e30f;
#pragma unroll
        for (int j = 0; j < 4; j++) {
            rm0 = fmaxf(rm0, fmaxf(sc[j][0], sc[j][1]));
            rm1 = fmaxf(rm1, fmaxf(sc[j][2], sc[j][3]));
        }
        rm0 = fmaxf(rm0, __shfl_xor_sync(0xffffffffu, rm0, 1));
        rm0 = fmaxf(rm0, __shfl_xor_sync(0xffffffffu, rm0, 2));
        rm1 = fmaxf(rm1, __shfl_xor_sync(0xffffffffu, rm1, 1));
        rm1 = fmaxf(rm1, __shfl_xor_sync(0xffffffffu, rm1, 2));
        float nm0 = fmaxf(m0, rm0), nm1 = fmaxf(m1, rm1);
        float a0 = __expf(m0 - nm0), a1 = __expf(m1 - nm1);
        float ls0 = 0.f, ls1 = 0.f;
#pragma unroll
        for (int j = 0; j < 4; j++) {
            sc[j][0] = __expf(sc[j][0] - nm0); ls0 += sc[j][0];
            sc[j][1] = __expf(sc[j][1] - nm0); ls0 += sc[j][1];
            sc[j][2] = __expf(sc[j][2] - nm1); ls1 += sc[j][2];
            sc[j][3] = __expf(sc[j][3] - nm1); ls1 += sc[j][3];
        }
        ls0 += __shfl_xor_sync(0xffffffffu, ls0, 1);
        ls0 += __shfl_xor_sync(0xffffffffu, ls0, 2);
        ls1 += __shfl_xor_sync(0xffffffffu, ls1, 1);
        ls1 += __shfl_xor_sync(0xffffffffu, ls1, 2);
        l0 = l0 * a0 + ls0;
        l1 = l1 * a1 + ls1;
        m0 = nm0; m1 = nm1;
#pragma unroll
        for (int j = 0; j < 8; j++) {
            O[j][0] *= a0; O[j][1] *= a0;
            O[j][2] *= a1; O[j][3] *= a1;
        }

        // ---- O += P V ----
#pragma unroll
        for (int t = 0; t < 2; t++) {
            unsigned ph[4];
            ph[0] = pack2(sc[2*t][0],   sc[2*t][1]);
            ph[1] = pack2(sc[2*t][2],   sc[2*t][3]);
            ph[2] = pack2(sc[2*t+1][0], sc[2*t+1][1]);
            ph[3] = pack2(sc[2*t+1][2], sc[2*t+1][3]);
            int rr = 16 * t + ((grp & 1) << 3) + li;
            int r7 = rr & 7;
#pragma unroll
            for (int jp = 0; jp < 4; jp++) {
                int sw = (((2 * jp + (grp >> 1)) ^ r7) << 4);
                unsigned v0, v1, v2, v3;
                ldsm4t(v0, v1, v2, v3, S + 4096 + rr * 128 + sw);
                mma4(O[2*jp],   ph, v0, v1);
                mma4(O[2*jp+1], ph, v2, v3);
            }
        }
        __syncthreads();
    }

    // ---- normalize + write (fp16 for proj) ----
    float inv0 = 1.f / l0, inv1 = 1.f / l1;
    int tok0 = b * THW + qr0 + mw + g;
#pragma unroll
    for (int j = 0; j < 8; j++) {
        int col = h * DA + j * 8 + 2 * tg;
        *(unsigned*)(g_ao + (size_t)tok0 * DD + col) =
            pack2(O[j][0] * inv0, O[j][1] * inv0);
        *(unsigned*)(g_ao + (size_t)(tok0 + 8) * DD + col) =
            pack2(O[j][2] * inv1, O[j][3] * inv1);
    }
}

// ---------------------------------------------------------------- launch
extern "C" void kernel_launch(void* const* d_in, const int* in_sizes, int n_in,
                              void* d_out, int out_size) {
    const float* x     = (const float*)d_in[0];
    const float* Bb    = (const float*)d_in[1];
    const int*   M     = (const int*)  d_in[2];
    const float* gamma = (const float*)d_in[3];
    const float* beta  = (const float*)d_in[4];
    const float* wq    = (const float*)d_in[5];
    const float* wk    = (const float*)d_in[6];
    const float* wv    = (const float*)d_in[7];
    const float* wp    = (const float*)d_in[8];
    float* out = (float*)d_out;

    cudaFuncSetAttribute(qkv_g,  cudaFuncAttributeMaxDynamicSharedMemorySize, 3 * STG);
    cudaFuncSetAttribute(proj_g, cudaFuncAttributeMaxDynamicSharedMemorySize, 3 * STG);

    ln_kernel<<<NROWS, 128>>>(x, gamma, beta);
    prep_w<<<24, 256>>>(wq, wk, wv);
    prep_wp<<<512, 256>>>(wp);
    qkv_g<<<dim3(NROWS / 128, NQKV / 64), 256, 3 * STG>>>();
    attn_kernel<<<dim3(THW / 128, NA * BSZ), 256>>>(Bb, M);
    proj_g<<<dim3(NROWS / 128, DD / 64), 256, 3 * STG>>>(x, out);
}

// round 13
// speedup vs baseline: 2.0123x; 1.5963x over previous
#include <cuda_runtime.h>
#include <cuda_fp16.h>

#define NA   8
#define BSZ  4
#define THW  1024
#define DD   512
#define DA   64
#define NROWS (BSZ*THW)   // 4096
#define NQKV (3*NA*DA)    // 1536
#define STG  24576        // GEMM stage: A 16K | B 8K
#define ASTG 24576        // attn stage: K 4K | V 4K | Bias 16K

// ---------------- device scratch (allocation forbidden) ----------------
__device__ __half g_x [NROWS*DD];                // normalized x, fp16
__device__ __half g_q [NA*NROWS*DA];             // q (pre-scaled 1/8)
__device__ __half g_k [NA*NROWS*DA];
__device__ __half g_v [NA*NROWS*DA];
__device__ __half g_ao[NROWS*DD];                // concat attn out
__device__ __half g_wt[NQKV*DD];                 // qkv weights [n][d]
__device__ __half g_wp[DD*DD];                   // proj weights [o][i]
__device__ unsigned g_mb[THW*32];                // mask bitpack [q][kword]

// ---------------- helpers ----------------
__device__ __forceinline__ void mma4(float c[4], const unsigned a[4], unsigned b0, unsigned b1) {
    asm volatile(
        "mma.sync.aligned.m16n8k16.row.col.f32.f16.f16.f32 "
        "{%0,%1,%2,%3}, {%4,%5,%6,%7}, {%8,%9}, {%0,%1,%2,%3};\n"
        : "+f"(c[0]), "+f"(c[1]), "+f"(c[2]), "+f"(c[3])
        : "r"(a[0]), "r"(a[1]), "r"(a[2]), "r"(a[3]), "r"(b0), "r"(b1));
}

__device__ __forceinline__ void ldsm4(unsigned& r0, unsigned& r1, unsigned& r2, unsigned& r3,
                                      const void* p) {
    unsigned addr = (unsigned)__cvta_generic_to_shared(p);
    asm volatile("ldmatrix.sync.aligned.m8n8.x4.shared.b16 {%0,%1,%2,%3}, [%4];"
                 : "=r"(r0), "=r"(r1), "=r"(r2), "=r"(r3) : "r"(addr));
}

__device__ __forceinline__ void ldsm4t(unsigned& r0, unsigned& r1, unsigned& r2, unsigned& r3,
                                       const void* p) {
    unsigned addr = (unsigned)__cvta_generic_to_shared(p);
    asm volatile("ldmatrix.sync.aligned.m8n8.x4.trans.shared.b16 {%0,%1,%2,%3}, [%4];"
                 : "=r"(r0), "=r"(r1), "=r"(r2), "=r"(r3) : "r"(addr));
}

__device__ __forceinline__ void cpa16(void* dst, const void* src) {
    unsigned d = (unsigned)__cvta_generic_to_shared(dst);
    asm volatile("cp.async.cg.shared.global [%0], [%1], 16;" :: "r"(d), "l"(src));
}
__device__ __forceinline__ void cp_commit() {
    asm volatile("cp.async.commit_group;" ::: "memory");
}
template<int N> __device__ __forceinline__ void cp_wait() {
    asm volatile("cp.async.wait_group %0;" :: "n"(N) : "memory");
}

__device__ __forceinline__ unsigned pack2(float a, float b) {
    __half2 h2; h2.x = __float2half_rn(a); h2.y = __float2half_rn(b);
    return *reinterpret_cast<unsigned*>(&h2);
}

// ---------------------------------------------------------------- LayerNorm
__global__ void ln_kernel(const float* __restrict__ x,
                          const float* __restrict__ gamma,
                          const float* __restrict__ beta) {
    int row = blockIdx.x;
    int t   = threadIdx.x;              // 128 threads
    const float* xr = x + (size_t)row * DD;
    float v[4];
    float s = 0.f;
#pragma unroll
    for (int i = 0; i < 4; i++) { v[i] = xr[i * 128 + t]; s += v[i]; }

    __shared__ float rbuf[4];
    __shared__ float stat;
#pragma unroll
    for (int o = 16; o > 0; o >>= 1) s += __shfl_xor_sync(0xffffffffu, s, o);
    if ((t & 31) == 0) rbuf[t >> 5] = s;
    __syncthreads();
    if (t == 0) stat = rbuf[0] + rbuf[1] + rbuf[2] + rbuf[3];
    __syncthreads();
    float mean = stat * (1.f / DD);

    float ss = 0.f;
#pragma unroll
    for (int i = 0; i < 4; i++) { float d = v[i] - mean; ss += d * d; }
    __syncthreads();
#pragma unroll
    for (int o = 16; o > 0; o >>= 1) ss += __shfl_xor_sync(0xffffffffu, ss, o);
    if ((t & 31) == 0) rbuf[t >> 5] = ss;
    __syncthreads();
    if (t == 0) stat = rbuf[0] + rbuf[1] + rbuf[2] + rbuf[3];
    __syncthreads();
    float rstd = rsqrtf(stat * (1.f / DD) + 1e-5f);

#pragma unroll
    for (int i = 0; i < 4; i++) {
        int c = i * 128 + t;
        float y = (v[i] - mean) * rstd * gamma[c] + beta[c];
        g_x[(size_t)row * DD + c] = __float2half_rn(y);
    }
}

// ------------------------------------------------- weight prep (smem transpose)
// grid (24, 8): block = (which,h) x d-chunk
__global__ void prep_w(const float* __restrict__ wq,
                       const float* __restrict__ wk,
                       const float* __restrict__ wv) {
    __shared__ float tile[64][65];
    int which = blockIdx.x >> 3, h = blockIdx.x & 7;
    const float* w = ((which == 0) ? wq : (which == 1) ? wk : wv) + (size_t)h * DD * DA;
    int n0 = which * 512 + h * 64;
    int d0 = blockIdx.y * 64;

#pragma unroll
    for (int it = 0; it < 16; it++) {
        int idx = it * 256 + threadIdx.x;    // 4096
        int r = idx >> 6, e = idx & 63;
        tile[r][e] = w[(size_t)(d0 + r) * DA + e];
    }
    __syncthreads();
#pragma unroll
    for (int it = 0; it < 8; it++) {
        int idx = it * 256 + threadIdx.x;    // 2048
        int e = idx >> 5, j = idx & 31;
        *(unsigned*)(g_wt + (size_t)(n0 + e) * DD + d0 + 2 * j) =
            pack2(tile[2 * j][e], tile[2 * j + 1][e]);
    }
}

__global__ void prep_wp(const float* __restrict__ wp) {
    size_t p = (size_t)blockIdx.x * 256 + threadIdx.x;   // grid 512
    float2 v = ((const float2*)wp)[p];
    ((unsigned*)g_wp)[p] = pack2(v.x, v.y);
}

// mask bitpack: word w covers k in [32(w&31), +32), row q = w>>5
__global__ void prep_m(const int* __restrict__ M) {
    int w = blockIdx.x * 256 + threadIdx.x;   // grid 128 -> 32768 words
    int q = w >> 5, c = w & 31;
    const int4* row = (const int4*)(M + (size_t)q * THW + c * 32);
    unsigned bits = 0;
#pragma unroll
    for (int i = 0; i < 8; i++) {
        int4 v = row[i];
        bits |= (unsigned)(v.x != 0) << (4 * i + 0);
        bits |= (unsigned)(v.y != 0) << (4 * i + 1);
        bits |= (unsigned)(v.z != 0) << (4 * i + 2);
        bits |= (unsigned)(v.w != 0) << (4 * i + 3);
    }
    g_mb[w] = bits;
}

// ---------------------------------------------------------------- big GEMM
// C[128m x 64n] per block, 8 warps (4m x 2n), warp 32x32, k-tile 64.
// 3-stage cp.async pipeline, stages of 24KB (A 16K | B 8K) dynamic smem.
struct GemmAcc { float c[2][4][4]; };

__device__ __forceinline__ void gemm_stage_load(
    const __half* Asrc, const __half* Bsrc, char* S, int tid, int k0)
{
#pragma unroll
    for (int it = 0; it < 4; it++) {
        int flat = it * 256 + tid;
        int r = flat >> 3, cc = flat & 7;
        size_t so = (size_t)r * DD + k0 + cc * 8;
        int off = r * 128 + ((cc ^ (r & 7)) << 4);
        cpa16(S + off, Asrc + so);
    }
#pragma unroll
    for (int it = 0; it < 2; it++) {
        int flat = it * 256 + tid;
        int r = flat >> 3, cc = flat & 7;
        size_t so = (size_t)r * DD + k0 + cc * 8;
        int off = r * 128 + ((cc ^ (r & 7)) << 4);
        cpa16(S + 16384 + off, Bsrc + so);
    }
    cp_commit();
}

__device__ __forceinline__ void gemm_stage_compute(
    char* S, int mw, int nw, int grp, int li, GemmAcc& acc)
{
    char* As = S;
    char* Bs = S + 16384;
#pragma unroll
    for (int s4 = 0; s4 < 4; s4++) {
        unsigned af[2][4];
#pragma unroll
        for (int mi = 0; mi < 2; mi++) {
            int ar = mw + mi * 16 + ((grp & 1) << 3) + li;
            int sw = (((s4 * 2 + (grp >> 1)) ^ (ar & 7)) << 4);
            ldsm4(af[mi][0], af[mi][1], af[mi][2], af[mi][3], As + ar * 128 + sw);
        }
        unsigned bf[2][4];
#pragma unroll
        for (int jp = 0; jp < 2; jp++) {
            int br = nw + jp * 16 + ((grp >> 1) << 3) + li;
            int sw = (((s4 * 2 + (grp & 1)) ^ (br & 7)) << 4);
            ldsm4(bf[jp][0], bf[jp][1], bf[jp][2], bf[jp][3], Bs + br * 128 + sw);
        }
#pragma unroll
        for (int mi = 0; mi < 2; mi++)
#pragma unroll
            for (int jp = 0; jp < 2; jp++) {
                mma4(acc.c[mi][jp * 2],     af[mi], bf[jp][0], bf[jp][1]);
                mma4(acc.c[mi][jp * 2 + 1], af[mi], bf[jp][2], bf[jp][3]);
            }
    }
}

__device__ __forceinline__ void gemm_mainloop(
    const __half* Asrc, const __half* Bsrc,
    char* sm, int tid, int mw, int nw, int grp, int li, GemmAcc& acc)
{
    const int NK = DD / 64;   // 8
    gemm_stage_load(Asrc, Bsrc, sm,       tid, 0);
    gemm_stage_load(Asrc, Bsrc, sm + STG, tid, 64);
#pragma unroll 1
    for (int kt = 0; kt < NK; kt++) {
        if (kt + 2 < NK) {
            gemm_stage_load(Asrc, Bsrc, sm + ((kt + 2) % 3) * STG, tid, (kt + 2) * 64);
            cp_wait<2>();
        } else if (kt + 1 < NK) {
            cp_wait<1>();
        } else {
            cp_wait<0>();
        }
        __syncthreads();
        gemm_stage_compute(sm + (kt % 3) * STG, mw, nw, grp, li, acc);
        __syncthreads();
    }
}

// qkv GEMM: grid (4096/128, 1536/64), 256 thr, dynamic smem 72KB
__global__ __launch_bounds__(256, 2) void qkv_g() {
    extern __shared__ __align__(16) char smd[];
    int m0 = blockIdx.x * 128, n0 = blockIdx.y * 64;
    int which = n0 >> 9, h = (n0 >> 6) & 7;

    int tid = threadIdx.x, lane = tid & 31, wid = tid >> 5;
    int g = lane >> 2, tg = lane & 3, grp = lane >> 3, li = lane & 7;
    int mw = (wid >> 1) * 32, nw = (wid & 1) * 32;

    GemmAcc acc = {};
    gemm_mainloop(g_x + (size_t)m0 * DD, g_wt + (size_t)n0 * DD,
                  smd, tid, mw, nw, grp, li, acc);

    float scale = (which == 0) ? 0.125f : 1.0f;
    __half* o = (which == 0) ? g_q : ((which == 1) ? g_k : g_v);
#pragma unroll
    for (int mi = 0; mi < 2; mi++)
#pragma unroll
        for (int nj = 0; nj < 4; nj++) {
            int m = m0 + mw + mi * 16 + g;
            int e = nw + nj * 8 + 2 * tg;
            size_t b0 = ((size_t)(h * NROWS + m)) * DA + e;
            size_t b1 = ((size_t)(h * NROWS + m + 8)) * DA + e;
            *(unsigned*)(o + b0) = pack2(acc.c[mi][nj][0] * scale, acc.c[mi][nj][1] * scale);
            *(unsigned*)(o + b1) = pack2(acc.c[mi][nj][2] * scale, acc.c[mi][nj][3] * scale);
        }
}

// proj GEMM + residual: grid (4096/128, 512/64), 256 thr, dynamic smem 72KB
__global__ __launch_bounds__(256, 2) void proj_g(const float* __restrict__ x,
                                                 float* __restrict__ out) {
    extern __shared__ __align__(16) char smd[];
    int m0 = blockIdx.x * 128, n0 = blockIdx.y * 64;

    int tid = threadIdx.x, lane = tid & 31, wid = tid >> 5;
    int g = lane >> 2, tg = lane & 3, grp = lane >> 3, li = lane & 7;
    int mw = (wid >> 1) * 32, nw = (wid & 1) * 32;

    GemmAcc acc = {};
    gemm_mainloop(g_ao + (size_t)m0 * DD, g_wp + (size_t)n0 * DD,
                  smd, tid, mw, nw, grp, li, acc);

#pragma unroll
    for (int mi = 0; mi < 2; mi++)
#pragma unroll
        for (int nj = 0; nj < 4; nj++) {
            int m = m0 + mw + mi * 16 + g;
            int n = n0 + nw + nj * 8 + 2 * tg;
#pragma unroll
            for (int rr = 0; rr < 2; rr++) {
                size_t off = (size_t)(m + rr * 8) * DD + n;
                float2 xr = *(const float2*)&x[off];
                float2 r;
                r.x = acc.c[mi][nj][rr * 2 + 0] + xr.x;
                r.y = acc.c[mi][nj][rr * 2 + 1] + xr.y;
                *(float2*)&out[off] = r;
            }
        }
}

// ---------------------------------------------------------------- fused attention
// grid (THW/128, NA*BSZ), 256 threads (8 warps, m16 each). k-tile = 32 tokens.
// Stage (24KB): K 4K | V 4K | Bias 16K, double-buffered (48KB static).
// Mask comes from the packed bitmask (2 broadcast LDG.32 per thread per tile).
__global__ __launch_bounds__(256) void attn_kernel(const float* __restrict__ Bb) {
    __shared__ __align__(16) char sm[2][ASTG];

    int hb = blockIdx.y;
    int h = hb >> 2, b = hb & 3;
    int qr0 = blockIdx.x * 128;

    int tid = threadIdx.x, lane = tid & 31, wid = tid >> 5;
    int g = lane >> 2, tg = lane & 3, grp = lane >> 3, li = lane & 7;
    int mw = wid * 16;

    size_t kv = (size_t)(h * NROWS + b * THW) * DA;
    const float* Bblk = Bb + ((size_t)hb * THW + qr0) * THW;   // [128 local rows][1024]

    // ---- Q tile into sm[0], extract frags ----
#pragma unroll
    for (int it = 0; it < 4; it++) {
        int flat = it * 256 + tid;
        int r = flat >> 3, cc = flat & 7;
        size_t so = kv + (size_t)(qr0 + r) * DA + cc * 8;
        int off = r * 128 + ((cc ^ (r & 7)) << 4);
        cpa16(sm[0] + off, g_q + so);
    }
    cp_commit();
    cp_wait<0>();
    __syncthreads();

    unsigned qf[4][4];
    {
        int qrow = mw + ((grp & 1) << 3) + li;
        int q7 = qrow & 7;
#pragma unroll
        for (int s4 = 0; s4 < 4; s4++) {
            int sw = (((s4 * 2 + (grp >> 1)) ^ q7) << 4);
            ldsm4(qf[s4][0], qf[s4][1], qf[s4][2], qf[s4][3], sm[0] + qrow * 128 + sw);
        }
    }
    __syncthreads();

    // per-thread fixed pieces of the stage-load pattern
    int pr = tid >> 3, pc = tid & 7;
    int poff = pr * 128 + ((pc ^ (pr & 7)) << 4);

    // stage loader: K @0, V @4096, Bias @8192 (swizzled 128B rows)
    auto load_stage = [&](char* S, int kt) {
        size_t so = kv + (size_t)(kt * 32 + pr) * DA + pc * 8;
        cpa16(S + poff,        g_k + so);
        cpa16(S + 4096 + poff, g_v + so);
#pragma unroll
        for (int it = 0; it < 4; it++) {
            int flat = it * 256 + tid;
            int r = flat >> 3, cc = flat & 7;
            cpa16(S + 8192 + r * 128 + ((cc ^ (r & 7)) << 4),
                  Bblk + (size_t)r * THW + kt * 32 + cc * 4);
        }
        cp_commit();
    };

    load_stage(sm[0], 0);

    float m0 = -1e30f, m1 = -1e30f, l0 = 0.f, l1 = 0.f;
    float O[8][4] = {};

    const unsigned* mrow0 = g_mb + (qr0 + mw + g) * 32;
    const unsigned* mrow1 = mrow0 + 8 * 32;
    // bias smem read addressing (conflict-free under swizzle; see analysis)
    int brow0 = mw + g, brow1 = brow0 + 8;
    int boff = 8 * (tg & 1);
    int bch  = tg >> 1;

    for (int kt = 0; kt < 32; kt++) {
        unsigned mk0 = mrow0[kt];
        unsigned mk1 = mrow1[kt];
        if (kt < 31) {
            load_stage(sm[(kt + 1) & 1], kt + 1);
            cp_wait<1>();
        } else {
            cp_wait<0>();
        }
        __syncthreads();
        char* S = sm[kt & 1];

        // ---- S = Q K^T, 32 kcols -> sc[4][4] ----
        float sc[4][4] = {};
#pragma unroll
        for (int s4 = 0; s4 < 4; s4++) {
#pragma unroll
            for (int jp = 0; jp < 2; jp++) {
                int rr = jp * 16 + ((grp >> 1) << 3) + li;
                int sw = (((s4 * 2 + (grp & 1)) ^ (rr & 7)) << 4);
                unsigned k0, k1, k2, k3;
                ldsm4(k0, k1, k2, k3, S + rr * 128 + sw);
                mma4(sc[2*jp],   qf[s4], k0, k1);
                mma4(sc[2*jp+1], qf[s4], k2, k3);
            }
        }

        // ---- bias (smem) + mask (bitmask) ----
        char* Bs = S + 8192;
#pragma unroll
        for (int j = 0; j < 4; j++) {
            int ch = bch + 2 * j;
            float2 b0 = *(const float2*)(Bs + brow0 * 128 + (((ch ^ (brow0 & 7))) << 4) + boff);
            float2 b1 = *(const float2*)(Bs + brow1 * 128 + (((ch ^ (brow1 & 7))) << 4) + boff);
            int bit = 8 * j + 2 * tg;
            sc[j][0] = (mk0 >> bit)       & 1 ? -10000.f : sc[j][0] + b0.x;
            sc[j][1] = (mk0 >> (bit + 1)) & 1 ? -10000.f : sc[j][1] + b0.y;
            sc[j][2] = (mk1 >> bit)       & 1 ? -10000.f : sc[j][2] + b1.x;
            sc[j][3] = (mk1 >> (bit + 1)) & 1 ? -10000.f : sc[j][3] + b1.y;
        }

        // ---- online softmax ----
        float rm0 = -1e30f, rm1 = -1e30f;
#pragma unroll
        for (int j = 0; j < 4; j++) {
            rm0 = fmaxf(rm0, fmaxf(sc[j][0], sc[j][1]));
            rm1 = fmaxf(rm1, fmaxf(sc[j][2], sc[j][3]));
        }
        rm0 = fmaxf(rm0, __shfl_xor_sync(0xffffffffu, rm0, 1));
        rm0 = fmaxf(rm0, __shfl_xor_sync(0xffffffffu, rm0, 2));
        rm1 = fmaxf(rm1, __shfl_xor_sync(0xffffffffu, rm1, 1));
        rm1 = fmaxf(rm1, __shfl_xor_sync(0xffffffffu, rm1, 2));
        float nm0 = fmaxf(m0, rm0), nm1 = fmaxf(m1, rm1);
        float a0 = __expf(m0 - nm0), a1 = __expf(m1 - nm1);
        float ls0 = 0.f, ls1 = 0.f;
#pragma unroll
        for (int j = 0; j < 4; j++) {
            sc[j][0] = __expf(sc[j][0] - nm0); ls0 += sc[j][0];
            sc[j][1] = __expf(sc[j][1] - nm0); ls0 += sc[j][1];
            sc[j][2] = __expf(sc[j][2] - nm1); ls1 += sc[j][2];
            sc[j][3] = __expf(sc[j][3] - nm1); ls1 += sc[j][3];
        }
        ls0 += __shfl_xor_sync(0xffffffffu, ls0, 1);
        ls0 += __shfl_xor_sync(0xffffffffu, ls0, 2);
        ls1 += __shfl_xor_sync(0xffffffffu, ls1, 1);
        ls1 += __shfl_xor_sync(0xffffffffu, ls1, 2);
        l0 = l0 * a0 + ls0;
        l1 = l1 * a1 + ls1;
        m0 = nm0; m1 = nm1;
#pragma unroll
        for (int j = 0; j < 8; j++) {
            O[j][0] *= a0; O[j][1] *= a0;
            O[j][2] *= a1; O[j][3] *= a1;
        }

        // ---- O += P V ----
#pragma unroll
        for (int t = 0; t < 2; t++) {
            unsigned ph[4];
            ph[0] = pack2(sc[2*t][0],   sc[2*t][1]);
            ph[1] = pack2(sc[2*t][2],   sc[2*t][3]);
            ph[2] = pack2(sc[2*t+1][0], sc[2*t+1][1]);
            ph[3] = pack2(sc[2*t+1][2], sc[2*t+1][3]);
            int rr = 16 * t + ((grp & 1) << 3) + li;
            int r7 = rr & 7;
#pragma unroll
            for (int jp = 0; jp < 4; jp++) {
                int sw = (((2 * jp + (grp >> 1)) ^ r7) << 4);
                unsigned v0, v1, v2, v3;
                ldsm4t(v0, v1, v2, v3, S + 4096 + rr * 128 + sw);
                mma4(O[2*jp],   ph, v0, v1);
                mma4(O[2*jp+1], ph, v2, v3);
            }
        }
        __syncthreads();
    }

    // ---- normalize + write (fp16 for proj) ----
    float inv0 = 1.f / l0, inv1 = 1.f / l1;
    int tok0 = b * THW + qr0 + mw + g;
#pragma unroll
    for (int j = 0; j < 8; j++) {
        int col = h * DA + j * 8 + 2 * tg;
        *(unsigned*)(g_ao + (size_t)tok0 * DD + col) =
            pack2(O[j][0] * inv0, O[j][1] * inv0);
        *(unsigned*)(g_ao + (size_t)(tok0 + 8) * DD + col) =
            pack2(O[j][2] * inv1, O[j][3] * inv1);
    }
}

// ---------------------------------------------------------------- launch
extern "C" void kernel_launch(void* const* d_in, const int* in_sizes, int n_in,
                              void* d_out, int out_size) {
    const float* x     = (const float*)d_in[0];
    const float* Bb    = (const float*)d_in[1];
    const int*   M     = (const int*)  d_in[2];
    const float* gamma = (const float*)d_in[3];
    const float* beta  = (const float*)d_in[4];
    const float* wq    = (const float*)d_in[5];
    const float* wk    = (const float*)d_in[6];
    const float* wv    = (const float*)d_in[7];
    const float* wp    = (const float*)d_in[8];
    float* out = (float*)d_out;

    cudaFuncSetAttribute(qkv_g,  cudaFuncAttributeMaxDynamicSharedMemorySize, 3 * STG);
    cudaFuncSetAttribute(proj_g, cudaFuncAttributeMaxDynamicSharedMemorySize, 3 * STG);

    ln_kernel<<<NROWS, 128>>>(x, gamma, beta);
    prep_w<<<dim3(24, 8), 256>>>(wq, wk, wv);
    prep_wp<<<512, 256>>>(wp);
    prep_m<<<128, 256>>>(M);
    qkv_g<<<dim3(NROWS / 128, NQKV / 64), 256, 3 * STG>>>();
    attn_kernel<<<dim3(THW / 128, NA * BSZ), 256>>>(Bb);
    proj_g<<<dim3(NROWS / 128, DD / 64), 256, 3 * STG>>>(x, out);
}

// round 14
// speedup vs baseline: 2.1499x; 1.0684x over previous
#include <cuda_runtime.h>
#include <cuda_fp16.h>

#define NA   8
#define BSZ  4
#define THW  1024
#define DD   512
#define DA   64
#define NROWS (BSZ*THW)   // 4096
#define NQKV (3*NA*DA)    // 1536
#define STG  32768        // GEMM stage: A 16K | B 16K  (128x128 tile)
#define ASTG 24576        // attn stage: K 4K | V 4K | Bias 16K

// ---------------- device scratch (allocation forbidden) ----------------
__device__ __half g_x [NROWS*DD];                // normalized x, fp16
__device__ __half g_q [NA*NROWS*DA];             // q (pre-scaled 1/8)
__device__ __half g_k [NA*NROWS*DA];
__device__ __half g_v [NA*NROWS*DA];
__device__ __half g_ao[NROWS*DD];                // concat attn out
__device__ __half g_wt[NQKV*DD];                 // qkv weights [n][d]
__device__ __half g_wp[DD*DD];                   // proj weights [o][i]
__device__ unsigned g_mb[THW*32];                // mask bitpack [q][kword]

// ---------------- helpers ----------------
__device__ __forceinline__ void mma4(float c[4], const unsigned a[4], unsigned b0, unsigned b1) {
    asm volatile(
        "mma.sync.aligned.m16n8k16.row.col.f32.f16.f16.f32 "
        "{%0,%1,%2,%3}, {%4,%5,%6,%7}, {%8,%9}, {%0,%1,%2,%3};\n"
        : "+f"(c[0]), "+f"(c[1]), "+f"(c[2]), "+f"(c[3])
        : "r"(a[0]), "r"(a[1]), "r"(a[2]), "r"(a[3]), "r"(b0), "r"(b1));
}

__device__ __forceinline__ void ldsm4(unsigned& r0, unsigned& r1, unsigned& r2, unsigned& r3,
                                      const void* p) {
    unsigned addr = (unsigned)__cvta_generic_to_shared(p);
    asm volatile("ldmatrix.sync.aligned.m8n8.x4.shared.b16 {%0,%1,%2,%3}, [%4];"
                 : "=r"(r0), "=r"(r1), "=r"(r2), "=r"(r3) : "r"(addr));
}

__device__ __forceinline__ void ldsm4t(unsigned& r0, unsigned& r1, unsigned& r2, unsigned& r3,
                                       const void* p) {
    unsigned addr = (unsigned)__cvta_generic_to_shared(p);
    asm volatile("ldmatrix.sync.aligned.m8n8.x4.trans.shared.b16 {%0,%1,%2,%3}, [%4];"
                 : "=r"(r0), "=r"(r1), "=r"(r2), "=r"(r3) : "r"(addr));
}

__device__ __forceinline__ void cpa16(void* dst, const void* src) {
    unsigned d = (unsigned)__cvta_generic_to_shared(dst);
    asm volatile("cp.async.cg.shared.global [%0], [%1], 16;" :: "r"(d), "l"(src));
}
__device__ __forceinline__ void cp_commit() {
    asm volatile("cp.async.commit_group;" ::: "memory");
}
template<int N> __device__ __forceinline__ void cp_wait() {
    asm volatile("cp.async.wait_group %0;" :: "n"(N) : "memory");
}

__device__ __forceinline__ unsigned pack2(float a, float b) {
    __half2 h2; h2.x = __float2half_rn(a); h2.y = __float2half_rn(b);
    return *reinterpret_cast<unsigned*>(&h2);
}

// ---------------------------------------------------------------- LayerNorm
__global__ void ln_kernel(const float* __restrict__ x,
                          const float* __restrict__ gamma,
                          const float* __restrict__ beta) {
    int row = blockIdx.x;
    int t   = threadIdx.x;              // 128 threads
    const float* xr = x + (size_t)row * DD;
    float v[4];
    float s = 0.f;
#pragma unroll
    for (int i = 0; i < 4; i++) { v[i] = xr[i * 128 + t]; s += v[i]; }

    __shared__ float rbuf[4];
    __shared__ float stat;
#pragma unroll
    for (int o = 16; o > 0; o >>= 1) s += __shfl_xor_sync(0xffffffffu, s, o);
    if ((t & 31) == 0) rbuf[t >> 5] = s;
    __syncthreads();
    if (t == 0) stat = rbuf[0] + rbuf[1] + rbuf[2] + rbuf[3];
    __syncthreads();
    float mean = stat * (1.f / DD);

    float ss = 0.f;
#pragma unroll
    for (int i = 0; i < 4; i++) { float d = v[i] - mean; ss += d * d; }
    __syncthreads();
#pragma unroll
    for (int o = 16; o > 0; o >>= 1) ss += __shfl_xor_sync(0xffffffffu, ss, o);
    if ((t & 31) == 0) rbuf[t >> 5] = ss;
    __syncthreads();
    if (t == 0) stat = rbuf[0] + rbuf[1] + rbuf[2] + rbuf[3];
    __syncthreads();
    float rstd = rsqrtf(stat * (1.f / DD) + 1e-5f);

#pragma unroll
    for (int i = 0; i < 4; i++) {
        int c = i * 128 + t;
        float y = (v[i] - mean) * rstd * gamma[c] + beta[c];
        g_x[(size_t)row * DD + c] = __float2half_rn(y);
    }
}

// ------------------------------------------------- unified prep kernel
// blocks [0,192): weight transpose (24 (which,h) x 8 d-chunks)
// blocks [192,224): proj weight convert
// blocks [224,4320): mask bitpack via warp ballot (one word per warp)
#define PW_BLKS 192
#define PWP_BLKS 32
__global__ void prep_all(const float* __restrict__ wq,
                         const float* __restrict__ wk,
                         const float* __restrict__ wv,
                         const float* __restrict__ wp,
                         const int* __restrict__ M) {
    int bx = blockIdx.x;
    if (bx < PW_BLKS) {
        __shared__ float tile[64][65];
        int wh = bx >> 3;                 // 0..23
        int which = wh >> 3, h = wh & 7;
        const float* w = ((which == 0) ? wq : (which == 1) ? wk : wv) + (size_t)h * DD * DA;
        int n0 = which * 512 + h * 64;
        int d0 = (bx & 7) * 64;
#pragma unroll
        for (int it = 0; it < 16; it++) {
            int idx = it * 256 + threadIdx.x;    // 4096
            int r = idx >> 6, e = idx & 63;
            tile[r][e] = w[(size_t)(d0 + r) * DA + e];
        }
        __syncthreads();
#pragma unroll
        for (int it = 0; it < 8; it++) {
            int idx = it * 256 + threadIdx.x;    // 2048
            int e = idx >> 5, j = idx & 31;
            *(unsigned*)(g_wt + (size_t)(n0 + e) * DD + d0 + 2 * j) =
                pack2(tile[2 * j][e], tile[2 * j + 1][e]);
        }
    } else if (bx < PW_BLKS + PWP_BLKS) {
        int base = (bx - PW_BLKS) * 256 + threadIdx.x;   // 8192 threads
#pragma unroll
        for (int i = 0; i < 16; i++) {
            int p = base + i * 8192;                     // 131072 float2 total
            float2 v = ((const float2*)wp)[p];
            ((unsigned*)g_wp)[p] = pack2(v.x, v.y);
        }
    } else {
        int w = (bx - PW_BLKS - PWP_BLKS) * 8 + (threadIdx.x >> 5);  // 32768 words
        int lane = threadIdx.x & 31;
        unsigned bits = __ballot_sync(0xffffffffu, M[(size_t)w * 32 + lane] != 0);
        if (lane == 0) g_mb[w] = bits;
    }
}

// ---------------------------------------------------------------- big GEMM
// C[128m x 128n] per block, 8 warps (4m x 2n), warp tile 32x64, k-tile 64.
// 3-stage cp.async pipeline, stages of 32KB (A 16K | B 16K) dynamic smem.
struct GemmAcc { float c[2][8][4]; };

__device__ __forceinline__ void gemm_stage_load(
    const __half* Asrc, const __half* Bsrc, char* S, int tid, int k0)
{
#pragma unroll
    for (int it = 0; it < 4; it++) {
        int flat = it * 256 + tid;
        int r = flat >> 3, cc = flat & 7;
        size_t so = (size_t)r * DD + k0 + cc * 8;
        int off = r * 128 + ((cc ^ (r & 7)) << 4);
        cpa16(S + off,         Asrc + so);
        cpa16(S + 16384 + off, Bsrc + so);
    }
    cp_commit();
}

__device__ __forceinline__ void gemm_stage_compute(
    char* S, int mw, int nw, int grp, int li, GemmAcc& acc)
{
    char* As = S;
    char* Bs = S + 16384;
#pragma unroll
    for (int s4 = 0; s4 < 4; s4++) {
        unsigned af[2][4];
#pragma unroll
        for (int mi = 0; mi < 2; mi++) {
            int ar = mw + mi * 16 + ((grp & 1) << 3) + li;
            int sw = (((s4 * 2 + (grp >> 1)) ^ (ar & 7)) << 4);
            ldsm4(af[mi][0], af[mi][1], af[mi][2], af[mi][3], As + ar * 128 + sw);
        }
        unsigned bf[4][4];
#pragma unroll
        for (int jp = 0; jp < 4; jp++) {
            int br = nw + jp * 16 + ((grp >> 1) << 3) + li;
            int sw = (((s4 * 2 + (grp & 1)) ^ (br & 7)) << 4);
            ldsm4(bf[jp][0], bf[jp][1], bf[jp][2], bf[jp][3], Bs + br * 128 + sw);
        }
#pragma unroll
        for (int mi = 0; mi < 2; mi++)
#pragma unroll
            for (int jp = 0; jp < 4; jp++) {
                mma4(acc.c[mi][jp * 2],     af[mi], bf[jp][0], bf[jp][1]);
                mma4(acc.c[mi][jp * 2 + 1], af[mi], bf[jp][2], bf[jp][3]);
            }
    }
}

__device__ __forceinline__ void gemm_mainloop(
    const __half* Asrc, const __half* Bsrc,
    char* sm, int tid, int mw, int nw, int grp, int li, GemmAcc& acc)
{
    const int NK = DD / 64;   // 8
    gemm_stage_load(Asrc, Bsrc, sm,       tid, 0);
    gemm_stage_load(Asrc, Bsrc, sm + STG, tid, 64);
#pragma unroll 1
    for (int kt = 0; kt < NK; kt++) {
        if (kt + 2 < NK) {
            gemm_stage_load(Asrc, Bsrc, sm + ((kt + 2) % 3) * STG, tid, (kt + 2) * 64);
            cp_wait<2>();
        } else if (kt + 1 < NK) {
            cp_wait<1>();
        } else {
            cp_wait<0>();
        }
        __syncthreads();
        gemm_stage_compute(sm + (kt % 3) * STG, mw, nw, grp, li, acc);
        __syncthreads();
    }
}

// qkv GEMM: grid (4096/128, 1536/128)=(32,12), 256 thr, dynamic smem 96KB
__global__ __launch_bounds__(256, 2) void qkv_g() {
    extern __shared__ __align__(16) char smd[];
    int m0 = blockIdx.x * 128, n0 = blockIdx.y * 128;

    int tid = threadIdx.x, lane = tid & 31, wid = tid >> 5;
    int g = lane >> 2, tg = lane & 3, grp = lane >> 3, li = lane & 7;
    int mw = (wid >> 1) * 32, nw = (wid & 1) * 64;

    GemmAcc acc = {};
    gemm_mainloop(g_x + (size_t)m0 * DD, g_wt + (size_t)n0 * DD,
                  smd, tid, mw, nw, grp, li, acc);

    int col0 = n0 + nw;                       // 64-aligned; constant per warp
    int which = col0 >> 9;
    int h = (col0 >> 6) & 7;
    float scale = (which == 0) ? 0.125f : 1.0f;
    __half* o = (which == 0) ? g_q : ((which == 1) ? g_k : g_v);
#pragma unroll
    for (int mi = 0; mi < 2; mi++)
#pragma unroll
        for (int nj = 0; nj < 8; nj++) {
            int m = m0 + mw + mi * 16 + g;
            int e = nj * 8 + 2 * tg;
            size_t b0 = ((size_t)(h * NROWS + m)) * DA + e;
            size_t b1 = ((size_t)(h * NROWS + m + 8)) * DA + e;
            *(unsigned*)(o + b0) = pack2(acc.c[mi][nj][0] * scale, acc.c[mi][nj][1] * scale);
            *(unsigned*)(o + b1) = pack2(acc.c[mi][nj][2] * scale, acc.c[mi][nj][3] * scale);
        }
}

// proj GEMM + residual: grid (32, 4), 256 thr, dynamic smem 96KB
__global__ __launch_bounds__(256, 2) void proj_g(const float* __restrict__ x,
                                                 float* __restrict__ out) {
    extern __shared__ __align__(16) char smd[];
    int m0 = blockIdx.x * 128, n0 = blockIdx.y * 128;

    int tid = threadIdx.x, lane = tid & 31, wid = tid >> 5;
    int g = lane >> 2, tg = lane & 3, grp = lane >> 3, li = lane & 7;
    int mw = (wid >> 1) * 32, nw = (wid & 1) * 64;

    GemmAcc acc = {};
    gemm_mainloop(g_ao + (size_t)m0 * DD, g_wp + (size_t)n0 * DD,
                  smd, tid, mw, nw, grp, li, acc);

#pragma unroll
    for (int mi = 0; mi < 2; mi++)
#pragma unroll
        for (int nj = 0; nj < 8; nj++) {
            int m = m0 + mw + mi * 16 + g;
            int n = n0 + nw + nj * 8 + 2 * tg;
#pragma unroll
            for (int rr = 0; rr < 2; rr++) {
                size_t off = (size_t)(m + rr * 8) * DD + n;
                float2 xr = *(const float2*)&x[off];
                float2 r;
                r.x = acc.c[mi][nj][rr * 2 + 0] + xr.x;
                r.y = acc.c[mi][nj][rr * 2 + 1] + xr.y;
                *(float2*)&out[off] = r;
            }
        }
}

// ---------------------------------------------------------------- fused attention
// grid (THW/128, NA*BSZ), 256 threads (8 warps, m16 each). k-tile = 32 tokens.
// Stage (24KB): K 4K | V 4K | Bias 16K, double-buffered (48KB static).
__global__ __launch_bounds__(256) void attn_kernel(const float* __restrict__ Bb) {
    __shared__ __align__(16) char sm[2][ASTG];

    int hb = blockIdx.y;
    int h = hb >> 2, b = hb & 3;
    int qr0 = blockIdx.x * 128;

    int tid = threadIdx.x, lane = tid & 31, wid = tid >> 5;
    int g = lane >> 2, tg = lane & 3, grp = lane >> 3, li = lane & 7;
    int mw = wid * 16;

    size_t kv = (size_t)(h * NROWS + b * THW) * DA;
    const float* Bblk = Bb + ((size_t)hb * THW + qr0) * THW;   // [128 local rows][1024]

    // ---- Q tile into sm[0], extract frags ----
#pragma unroll
    for (int it = 0; it < 4; it++) {
        int flat = it * 256 + tid;
        int r = flat >> 3, cc = flat & 7;
        size_t so = kv + (size_t)(qr0 + r) * DA + cc * 8;
        int off = r * 128 + ((cc ^ (r & 7)) << 4);
        cpa16(sm[0] + off, g_q + so);
    }
    cp_commit();
    cp_wait<0>();
    __syncthreads();

    unsigned qf[4][4];
    {
        int qrow = mw + ((grp & 1) << 3) + li;
        int q7 = qrow & 7;
#pragma unroll
        for (int s4 = 0; s4 < 4; s4++) {
            int sw = (((s4 * 2 + (grp >> 1)) ^ q7) << 4);
            ldsm4(qf[s4][0], qf[s4][1], qf[s4][2], qf[s4][3], sm[0] + qrow * 128 + sw);
        }
    }
    __syncthreads();

    // per-thread fixed pieces of the stage-load pattern
    int pr = tid >> 3, pc = tid & 7;
    int poff = pr * 128 + ((pc ^ (pr & 7)) << 4);

    // stage loader: K @0, V @4096, Bias @8192 (swizzled 128B rows)
    auto load_stage = [&](char* S, int kt) {
        size_t so = kv + (size_t)(kt * 32 + pr) * DA + pc * 8;
        cpa16(S + poff,        g_k + so);
        cpa16(S + 4096 + poff, g_v + so);
#pragma unroll
        for (int it = 0; it < 4; it++) {
            int flat = it * 256 + tid;
            int r = flat >> 3, cc = flat & 7;
            cpa16(S + 8192 + r * 128 + ((cc ^ (r & 7)) << 4),
                  Bblk + (size_t)r * THW + kt * 32 + cc * 4);
        }
        cp_commit();
    };

    load_stage(sm[0], 0);

    float m0 = -1e30f, m1 = -1e30f, l0 = 0.f, l1 = 0.f;
    float O[8][4] = {};

    const unsigned* mrow0 = g_mb + (qr0 + mw + g) * 32;
    const unsigned* mrow1 = mrow0 + 8 * 32;
    int brow0 = mw + g, brow1 = brow0 + 8;
    int boff = 8 * (tg & 1);
    int bch  = tg >> 1;

    for (int kt = 0; kt < 32; kt++) {
        unsigned mk0 = mrow0[kt];
        unsigned mk1 = mrow1[kt];
        if (kt < 31) {
            load_stage(sm[(kt + 1) & 1], kt + 1);
            cp_wait<1>();
        } else {
            cp_wait<0>();
        }
        __syncthreads();
        char* S = sm[kt & 1];

        // ---- S = Q K^T, 32 kcols -> sc[4][4] ----
        float sc[4][4] = {};
#pragma unroll
        for (int s4 = 0; s4 < 4; s4++) {
#pragma unroll
            for (int jp = 0; jp < 2; jp++) {
                int rr = jp * 16 + ((grp >> 1) << 3) + li;
                int sw = (((s4 * 2 + (grp & 1)) ^ (rr & 7)) << 4);
                unsigned k0, k1, k2, k3;
                ldsm4(k0, k1, k2, k3, S + rr * 128 + sw);
                mma4(sc[2*jp],   qf[s4], k0, k1);
                mma4(sc[2*jp+1], qf[s4], k2, k3);
            }
        }

        // ---- bias (smem) + mask (bitmask) ----
        char* Bs = S + 8192;
#pragma unroll
        for (int j = 0; j < 4; j++) {
            int ch = bch + 2 * j;
            float2 b0 = *(const float2*)(Bs + brow0 * 128 + (((ch ^ (brow0 & 7))) << 4) + boff);
            float2 b1 = *(const float2*)(Bs + brow1 * 128 + (((ch ^ (brow1 & 7))) << 4) + boff);
            int bit = 8 * j + 2 * tg;
            sc[j][0] = (mk0 >> bit)       & 1 ? -10000.f : sc[j][0] + b0.x;
            sc[j][1] = (mk0 >> (bit + 1)) & 1 ? -10000.f : sc[j][1] + b0.y;
            sc[j][2] = (mk1 >> bit)       & 1 ? -10000.f : sc[j][2] + b1.x;
            sc[j][3] = (mk1 >> (bit + 1)) & 1 ? -10000.f : sc[j][3] + b1.y;
        }

        // ---- online softmax ----
        float rm0 = -1e30f, rm1 = -1e30f;
#pragma unroll
        for (int j = 0; j < 4; j++) {
            rm0 = fmaxf(rm0, fmaxf(sc[j][0], sc[j][1]));
            rm1 = fmaxf(rm1, fmaxf(sc[j][2], sc[j][3]));
        }
        rm0 = fmaxf(rm0, __shfl_xor_sync(0xffffffffu, rm0, 1));
        rm0 = fmaxf(rm0, __shfl_xor_sync(0xffffffffu, rm0, 2));
        rm1 = fmaxf(rm1, __shfl_xor_sync(0xffffffffu, rm1, 1));
        rm1 = fmaxf(rm1, __shfl_xor_sync(0xffffffffu, rm1, 2));
        float nm0 = fmaxf(m0, rm0), nm1 = fmaxf(m1, rm1);
        float a0 = __expf(m0 - nm0), a1 = __expf(m1 - nm1);
        float ls0 = 0.f, ls1 = 0.f;
#pragma unroll
        for (int j = 0; j < 4; j++) {
            sc[j][0] = __expf(sc[j][0] - nm0); ls0 += sc[j][0];
            sc[j][1] = __expf(sc[j][1] - nm0); ls0 += sc[j][1];
            sc[j][2] = __expf(sc[j][2] - nm1); ls1 += sc[j][2];
            sc[j][3] = __expf(sc[j][3] - nm1); ls1 += sc[j][3];
        }
        ls0 += __shfl_xor_sync(0xffffffffu, ls0, 1);
        ls0 += __shfl_xor_sync(0xffffffffu, ls0, 2);
        ls1 += __shfl_xor_sync(0xffffffffu, ls1, 1);
        ls1 += __shfl_xor_sync(0xffffffffu, ls1, 2);
        l0 = l0 * a0 + ls0;
        l1 = l1 * a1 + ls1;
        m0 = nm0; m1 = nm1;
#pragma unroll
        for (int j = 0; j < 8; j++) {
            O[j][0] *= a0; O[j][1] *= a0;
            O[j][2] *= a1; O[j][3] *= a1;
        }

        // ---- O += P V ----
#pragma unroll
        for (int t = 0; t < 2; t++) {
            unsigned ph[4];
            ph[0] = pack2(sc[2*t][0],   sc[2*t][1]);
            ph[1] = pack2(sc[2*t][2],   sc[2*t][3]);
            ph[2] = pack2(sc[2*t+1][0], sc[2*t+1][1]);
            ph[3] = pack2(sc[2*t+1][2], sc[2*t+1][3]);
            int rr = 16 * t + ((grp & 1) << 3) + li;
            int r7 = rr & 7;
#pragma unroll
            for (int jp = 0; jp < 4; jp++) {
                int sw = (((2 * jp + (grp >> 1)) ^ r7) << 4);
                unsigned v0, v1, v2, v3;
                ldsm4t(v0, v1, v2, v3, S + 4096 + rr * 128 + sw);
                mma4(O[2*jp],   ph, v0, v1);
                mma4(O[2*jp+1], ph, v2, v3);
            }
        }
        __syncthreads();
    }

    // ---- normalize + write (fp16 for proj) ----
    float inv0 = 1.f / l0, inv1 = 1.f / l1;
    int tok0 = b * THW + qr0 + mw + g;
#pragma unroll
    for (int j = 0; j < 8; j++) {
        int col = h * DA + j * 8 + 2 * tg;
        *(unsigned*)(g_ao + (size_t)tok0 * DD + col) =
            pack2(O[j][0] * inv0, O[j][1] * inv0);
        *(unsigned*)(g_ao + (size_t)(tok0 + 8) * DD + col) =
            pack2(O[j][2] * inv1, O[j][3] * inv1);
    }
}

// ---------------------------------------------------------------- launch
extern "C" void kernel_launch(void* const* d_in, const int* in_sizes, int n_in,
                              void* d_out, int out_size) {
    const float* x     = (const float*)d_in[0];
    const float* Bb    = (const float*)d_in[1];
    const int*   M     = (const int*)  d_in[2];
    const float* gamma = (const float*)d_in[3];
    const float* beta  = (const float*)d_in[4];
    const float* wq    = (const float*)d_in[5];
    const float* wk    = (const float*)d_in[6];
    const float* wv    = (const float*)d_in[7];
    const float* wp    = (const float*)d_in[8];
    float* out = (float*)d_out;

    cudaFuncSetAttribute(qkv_g,  cudaFuncAttributeMaxDynamicSharedMemorySize, 3 * STG);
    cudaFuncSetAttribute(proj_g, cudaFuncAttributeMaxDynamicSharedMemorySize, 3 * STG);

    ln_kernel<<<NROWS, 128>>>(x, gamma, beta);
    prep_all<<<PW_BLKS + PWP_BLKS + 4096, 256>>>(wq, wk, wv, wp, M);
    qkv_g<<<dim3(NROWS / 128, NQKV / 128), 256, 3 * STG>>>();
    attn_kernel<<<dim3(THW / 128, NA * BSZ), 256>>>(Bb);
    proj_g<<<dim3(NROWS / 128, DD / 128), 256, 3 * STG>>>(x, out);
}